// round 1
// baseline (speedup 1.0000x reference)
#include <cuda_runtime.h>
#include <cuda_bf16.h>
#include <math.h>

// Problem constants
#define BATCH 2
#define SEQ   2048
#define EMBED 2048
#define HEADS 16
#define DK    128
#define TOKENS (BATCH * SEQ)          // 4096
#define QKV_N  (3 * EMBED)            // 6144

// ---------------- scratch (device globals; no allocation) ----------------
__device__ float g_qkv [(size_t)TOKENS * QKV_N];            // 4096 x 6144
__device__ float g_q   [(size_t)BATCH * HEADS * SEQ * DK];  // head-major
__device__ float g_k   [(size_t)BATCH * HEADS * SEQ * DK];
__device__ float g_v   [(size_t)BATCH * HEADS * SEQ * DK];
__device__ float g_attn[(size_t)TOKENS * EMBED];            // token-major

// =====================================================================
// Kernel 1/4: tiled SGEMM with bias.  C[M,N] = A[M,K] @ B[K,N] + bias[N]
// BM=BN=128, BK=16, 256 threads, 8x8 per thread. M,N,K multiples of 128/16.
// =====================================================================
__global__ __launch_bounds__(256)
void sgemm_bias(const float* __restrict__ A, const float* __restrict__ B,
                const float* __restrict__ bias, float* __restrict__ C,
                int M, int N, int K) {
    __shared__ float As[16][128];
    __shared__ float Bs[16][128];

    const int tid = threadIdx.x;
    const int bx = blockIdx.x, by = blockIdx.y;
    const int tx = tid & 15, ty = tid >> 4;

    const int arow = tid >> 1;          // 0..127
    const int kg   = (tid & 1) * 8;     // 0 or 8
    const int brow = tid >> 5;          // 0..7
    const int bcol = (tid & 31) * 4;    // 0..124

    const float* Ap = A + (size_t)(by * 128 + arow) * K + kg;
    const float* Bp = B + (size_t)brow * N + bx * 128 + bcol;

    float acc[8][8];
    #pragma unroll
    for (int i = 0; i < 8; i++)
        #pragma unroll
        for (int j = 0; j < 8; j++) acc[i][j] = 0.0f;

    for (int k0 = 0; k0 < K; k0 += 16) {
        const float4 a0 = *(const float4*)(Ap + k0);
        const float4 a1 = *(const float4*)(Ap + k0 + 4);
        const float4 b0 = *(const float4*)(Bp + (size_t)k0 * N);
        const float4 b1 = *(const float4*)(Bp + (size_t)(k0 + 8) * N);

        As[kg + 0][arow] = a0.x; As[kg + 1][arow] = a0.y;
        As[kg + 2][arow] = a0.z; As[kg + 3][arow] = a0.w;
        As[kg + 4][arow] = a1.x; As[kg + 5][arow] = a1.y;
        As[kg + 6][arow] = a1.z; As[kg + 7][arow] = a1.w;
        *(float4*)&Bs[brow][bcol]     = b0;
        *(float4*)&Bs[brow + 8][bcol] = b1;
        __syncthreads();

        #pragma unroll
        for (int kk = 0; kk < 16; kk++) {
            float a[8], b[8];
            *(float4*)(a)     = *(const float4*)&As[kk][ty * 8];
            *(float4*)(a + 4) = *(const float4*)&As[kk][ty * 8 + 4];
            *(float4*)(b)     = *(const float4*)&Bs[kk][tx * 8];
            *(float4*)(b + 4) = *(const float4*)&Bs[kk][tx * 8 + 4];
            #pragma unroll
            for (int i = 0; i < 8; i++)
                #pragma unroll
                for (int j = 0; j < 8; j++)
                    acc[i][j] += a[i] * b[j];
        }
        __syncthreads();
    }

    #pragma unroll
    for (int i = 0; i < 8; i++) {
        const size_t row = (size_t)(by * 128 + ty * 8 + i);
        #pragma unroll
        for (int jv = 0; jv < 8; jv += 4) {
            const int col = bx * 128 + tx * 8 + jv;
            float4 v;
            v.x = acc[i][jv + 0] + bias[col + 0];
            v.y = acc[i][jv + 1] + bias[col + 1];
            v.z = acc[i][jv + 2] + bias[col + 2];
            v.w = acc[i][jv + 3] + bias[col + 3];
            *(float4*)(C + row * N + col) = v;
        }
    }
}

// =====================================================================
// Kernel 2/4: split qkv into head-major Q/K/V with RoPE on Q,K.
// grid = (4096 tokens, 16 heads), 128 threads.
// Replicates reference bf16-theta chain exactly:
//   base = bf16(10000)=9984; t = bf16(base^(i/64)); theta = f32(bf16(1/t))
// freq = n * theta (f32); sin/cos of the f32 value, reduced mod 2pi in double.
// =====================================================================
__global__ __launch_bounds__(128)
void rope_split(const float* __restrict__ qkv, float* __restrict__ Q,
                float* __restrict__ K, float* __restrict__ V) {
    const int r = blockIdx.x;            // token 0..4095
    const int h = blockIdx.y;            // head 0..15
    const int b = r >> 11;
    const int n = r & 2047;
    const int i = threadIdx.x;           // 0..127

    const float* base = qkv + (size_t)r * QKV_N + h * DK;
    const size_t o = ((size_t)((b << 4) + h) * SEQ + n) * DK;

    V[o + i] = base[2 * EMBED + i];

    if (i < 64) {
        const float bf_base = __bfloat162float(__float2bfloat16(10000.0f)); // 9984
        const float e  = (float)i * (1.0f / 64.0f);
        const float pf = (float)pow((double)bf_base, (double)e);
        const float den = __bfloat162float(__float2bfloat16(pf));
        const float invf = __fdiv_rn(1.0f, den);
        const float theta = __bfloat162float(__float2bfloat16(invf));

        const float  freq = (float)n * theta;                  // f32 mult (exact op)
        const double fd = (double)freq;
        const double kq = rint(fd * 0.15915494309189535);      // /2pi
        const float  rr = (float)(fd - kq * 6.283185307179586);
        const float  s = sinf(rr);
        const float  c = cosf(rr);

        const float q1 = base[i],          q2 = base[i + 64];
        const float k1 = base[EMBED + i],  k2 = base[EMBED + i + 64];
        Q[o + i]      = q1 * c - q2 * s;
        Q[o + i + 64] = q1 * s + q2 * c;
        K[o + i]      = k1 * c - k2 * s;
        K[o + i + 64] = k1 * s + k2 * c;
    }
}

// =====================================================================
// Kernel 3/4: causal flash attention, fp32.
// grid = (32 q-tiles, 32 batch*head), 256 threads.
// 64-query tile, 64-key iteration, d=128.
// Q,K stored d-major in smem ([128][68]) for conflict-free float4 LDS.
// Each thread: 4x4 S tile (tx,ty in 16x16), 4 rows x 8 cols of O.
// =====================================================================
#define FA_SMEM_FLOATS (128 * 68 + 128 * 68 + 64 * 132 + 64 * 68)
#define FA_SMEM_BYTES  (FA_SMEM_FLOATS * 4)

__global__ __launch_bounds__(256)
void flash_attn(const float* __restrict__ Q, const float* __restrict__ K,
                const float* __restrict__ V, float* __restrict__ O) {
    const int qt = blockIdx.x;           // 0..31
    const int bh = blockIdx.y;           // 0..31
    const int b = bh >> 4, h = bh & 15;
    const int tid = threadIdx.x;
    const int tx = tid & 15, ty = tid >> 4;

    extern __shared__ float sm[];
    float* Qs = sm;                      // [128][68]  (d-major)
    float* Ks = Qs + 128 * 68;           // [128][68]  (d-major)
    float* Vs = Ks + 128 * 68;           // [64][132]  (kv-major)
    float* Ps = Vs + 64 * 132;           // [64][68]

    const size_t hb = (size_t)bh * SEQ * DK;
    const float* Qg = Q + hb + (size_t)qt * 64 * DK;

    // Load Q transposed into [d][m]
    for (int e = tid; e < 64 * 32; e += 256) {
        const int m = e & 63, dg = (e >> 6) << 2;
        const float4 v = *(const float4*)(Qg + m * DK + dg);
        Qs[(dg + 0) * 68 + m] = v.x;
        Qs[(dg + 1) * 68 + m] = v.y;
        Qs[(dg + 2) * 68 + m] = v.z;
        Qs[(dg + 3) * 68 + m] = v.w;
    }

    float m_r[4], l_r[4], o[4][8];
    #pragma unroll
    for (int i = 0; i < 4; i++) {
        m_r[i] = -1e30f; l_r[i] = 0.0f;
        #pragma unroll
        for (int j = 0; j < 8; j++) o[i][j] = 0.0f;
    }
    const float scale = 0.08838834764831845f;  // 1/sqrt(128)

    for (int kt = 0; kt <= qt; kt++) {
        __syncthreads();  // prior iteration done with Ks/Vs/Ps
        const float* Kg = K + hb + (size_t)kt * 64 * DK;
        const float* Vg = V + hb + (size_t)kt * 64 * DK;
        for (int e = tid; e < 2048; e += 256) {
            const int m = e & 63, dg = (e >> 6) << 2;
            const float4 v = *(const float4*)(Kg + m * DK + dg);
            Ks[(dg + 0) * 68 + m] = v.x;
            Ks[(dg + 1) * 68 + m] = v.y;
            Ks[(dg + 2) * 68 + m] = v.z;
            Ks[(dg + 3) * 68 + m] = v.w;
        }
        for (int e = tid; e < 2048; e += 256) {
            const int m = e >> 5, dg = (e & 31) << 2;
            *(float4*)(Vs + m * 132 + dg) = *(const float4*)(Vg + m * DK + dg);
        }
        __syncthreads();

        // S = Q K^T (4x4 per thread)
        float s[4][4];
        #pragma unroll
        for (int i = 0; i < 4; i++)
            #pragma unroll
            for (int j = 0; j < 4; j++) s[i][j] = 0.0f;

        #pragma unroll 8
        for (int k = 0; k < 128; k++) {
            const float4 qv = *(const float4*)&Qs[k * 68 + ty * 4];
            const float4 kv = *(const float4*)&Ks[k * 68 + tx * 4];
            const float aq[4] = {qv.x, qv.y, qv.z, qv.w};
            const float ak[4] = {kv.x, kv.y, kv.z, kv.w};
            #pragma unroll
            for (int i = 0; i < 4; i++)
                #pragma unroll
                for (int j = 0; j < 4; j++)
                    s[i][j] += aq[i] * ak[j];
        }

        // scale + causal mask (diagonal tile only)
        const int qbase = qt * 64 + ty * 4;
        const int kbase = kt * 64 + tx * 4;
        #pragma unroll
        for (int i = 0; i < 4; i++)
            #pragma unroll
            for (int j = 0; j < 4; j++) {
                float sv = s[i][j] * scale;
                if (kt == qt && (kbase + j) > (qbase + i)) sv = -1e30f;
                s[i][j] = sv;
            }

        // row max across 16 lanes (tx)
        float rmax[4];
        #pragma unroll
        for (int i = 0; i < 4; i++) {
            float v = fmaxf(fmaxf(s[i][0], s[i][1]), fmaxf(s[i][2], s[i][3]));
            #pragma unroll
            for (int off = 1; off < 16; off <<= 1)
                v = fmaxf(v, __shfl_xor_sync(0xffffffffu, v, off));
            rmax[i] = v;
        }

        float alpha[4];
        #pragma unroll
        for (int i = 0; i < 4; i++) {
            const float mn = fmaxf(m_r[i], rmax[i]);
            alpha[i] = __expf(m_r[i] - mn);
            m_r[i] = mn;
        }

        float rsum[4];
        #pragma unroll
        for (int i = 0; i < 4; i++) {
            float rs = 0.0f;
            #pragma unroll
            for (int j = 0; j < 4; j++) {
                const float p = __expf(s[i][j] - m_r[i]);
                s[i][j] = p; rs += p;
            }
            #pragma unroll
            for (int off = 1; off < 16; off <<= 1)
                rs += __shfl_xor_sync(0xffffffffu, rs, off);
            rsum[i] = rs;
        }

        #pragma unroll
        for (int i = 0; i < 4; i++) {
            l_r[i] = l_r[i] * alpha[i] + rsum[i];
            #pragma unroll
            for (int j = 0; j < 8; j++) o[i][j] *= alpha[i];
        }

        // write P, then O += P V
        #pragma unroll
        for (int i = 0; i < 4; i++)
            #pragma unroll
            for (int j = 0; j < 4; j++)
                Ps[(ty * 4 + i) * 68 + tx * 4 + j] = s[i][j];
        __syncthreads();

        #pragma unroll 4
        for (int kv = 0; kv < 64; kv++) {
            float pv[4];
            #pragma unroll
            for (int i = 0; i < 4; i++) pv[i] = Ps[(ty * 4 + i) * 68 + kv];
            const float4 v0 = *(const float4*)&Vs[kv * 132 + tx * 8];
            const float4 v1 = *(const float4*)&Vs[kv * 132 + tx * 8 + 4];
            const float av[8] = {v0.x, v0.y, v0.z, v0.w, v1.x, v1.y, v1.z, v1.w};
            #pragma unroll
            for (int i = 0; i < 4; i++)
                #pragma unroll
                for (int j = 0; j < 8; j++)
                    o[i][j] += pv[i] * av[j];
        }
    }

    // epilogue: normalize + write token-major [b][n][h*128 + c]
    float* Ob = O + ((size_t)(b * SEQ + qt * 64) * EMBED) + h * DK;
    #pragma unroll
    for (int i = 0; i < 4; i++) {
        const float inv = 1.0f / l_r[i];
        const int row = ty * 4 + i;
        float4 w0, w1;
        w0.x = o[i][0] * inv; w0.y = o[i][1] * inv;
        w0.z = o[i][2] * inv; w0.w = o[i][3] * inv;
        w1.x = o[i][4] * inv; w1.y = o[i][5] * inv;
        w1.z = o[i][6] * inv; w1.w = o[i][7] * inv;
        *(float4*)(Ob + (size_t)row * EMBED + tx * 8)     = w0;
        *(float4*)(Ob + (size_t)row * EMBED + tx * 8 + 4) = w1;
    }
}

// =====================================================================
// launch
// =====================================================================
extern "C" void kernel_launch(void* const* d_in, const int* in_sizes, int n_in,
                              void* d_out, int out_size) {
    // Map inputs by element count (robust to ordering):
    // x: 8388608, W_qkv: 12582912, b_qkv: 6144, W_o: 4194304, b_o: 2048
    const float *x = nullptr, *Wqkv = nullptr, *bqkv = nullptr,
                *Wo = nullptr, *bo = nullptr;
    for (int i = 0; i < n_in; i++) {
        switch (in_sizes[i]) {
            case 8388608:  x    = (const float*)d_in[i]; break;
            case 12582912: Wqkv = (const float*)d_in[i]; break;
            case 6144:     bqkv = (const float*)d_in[i]; break;
            case 4194304:  Wo   = (const float*)d_in[i]; break;
            case 2048:     bo   = (const float*)d_in[i]; break;
        }
    }
    float* out = (float*)d_out;

    float *qkv, *q, *k, *v, *attn;
    cudaGetSymbolAddress((void**)&qkv,  g_qkv);
    cudaGetSymbolAddress((void**)&q,    g_q);
    cudaGetSymbolAddress((void**)&k,    g_k);
    cudaGetSymbolAddress((void**)&v,    g_v);
    cudaGetSymbolAddress((void**)&attn, g_attn);

    // 1) qkv = x @ W_qkv + b_qkv
    sgemm_bias<<<dim3(QKV_N / 128, TOKENS / 128), 256>>>(
        x, Wqkv, bqkv, qkv, TOKENS, QKV_N, EMBED);

    // 2) split + RoPE
    rope_split<<<dim3(TOKENS, HEADS), 128>>>(qkv, q, k, v);

    // 3) causal flash attention
    cudaFuncSetAttribute(flash_attn, cudaFuncAttributeMaxDynamicSharedMemorySize,
                         FA_SMEM_BYTES);
    flash_attn<<<dim3(SEQ / 64, BATCH * HEADS), 256, FA_SMEM_BYTES>>>(
        q, k, v, attn);

    // 4) out = attn @ W_o + b_o
    sgemm_bias<<<dim3(EMBED / 128, TOKENS / 128), 256>>>(
        attn, Wo, bo, out, TOKENS, EMBED, EMBED);
}

// round 5
// speedup vs baseline: 1.6538x; 1.6538x over previous
#include <cuda_runtime.h>
#include <cuda_fp16.h>
#include <cuda_bf16.h>
#include <stdint.h>
#include <math.h>

// Problem constants
#define BATCH 2
#define SEQ   2048
#define EMBED 2048
#define HEADS 16
#define DK    128
#define TOKENS (BATCH * SEQ)          // 4096
#define QKV_N  (3 * EMBED)            // 6144

// ---------------- scratch (device globals; no allocation) ----------------
__device__ float g_qkv [(size_t)TOKENS * QKV_N];            // fp32 QKV
__device__ float g_q   [(size_t)BATCH * HEADS * SEQ * DK];
__device__ float g_k   [(size_t)BATCH * HEADS * SEQ * DK];
__device__ float g_v   [(size_t)BATCH * HEADS * SEQ * DK];

// split fp16 operands
__device__ __half g_xh [(size_t)TOKENS * EMBED];
__device__ __half g_xl [(size_t)TOKENS * EMBED];
__device__ __half g_wqh[(size_t)EMBED * QKV_N];
__device__ __half g_wql[(size_t)EMBED * QKV_N];
__device__ __half g_ah [(size_t)TOKENS * EMBED];   // attn out hi (from flash_attn)
__device__ __half g_al [(size_t)TOKENS * EMBED];   // attn out lo
__device__ __half g_woh[(size_t)EMBED * EMBED];
__device__ __half g_wol[(size_t)EMBED * EMBED];

// =====================================================================
// split fp32 -> (hi, lo) fp16.  a ~= hi + lo with ~22-bit precision.
// =====================================================================
__global__ __launch_bounds__(256)
void split_kernel(const float* __restrict__ a, __half* __restrict__ hi,
                  __half* __restrict__ lo, int n) {
    int i = (blockIdx.x * 256 + threadIdx.x) * 4;
    if (i >= n) return;
    float4 v = *(const float4*)(a + i);
    __half h0 = __float2half_rn(v.x);
    __half h1 = __float2half_rn(v.y);
    __half h2 = __float2half_rn(v.z);
    __half h3 = __float2half_rn(v.w);
    __half l0 = __float2half_rn(v.x - __half2float(h0));
    __half l1 = __float2half_rn(v.y - __half2float(h1));
    __half l2 = __float2half_rn(v.z - __half2float(h2));
    __half l3 = __float2half_rn(v.w - __half2float(h3));
    __half2* hp = (__half2*)(hi + i);
    __half2* lp = (__half2*)(lo + i);
    hp[0] = __halves2half2(h0, h1);
    hp[1] = __halves2half2(h2, h3);
    lp[0] = __halves2half2(l0, l1);
    lp[1] = __halves2half2(l2, l3);
}

// =====================================================================
// asm helpers (non-template, plain unsigned types)
// =====================================================================
__device__ __forceinline__ void cp16(unsigned dst, const void* src) {
    asm volatile("cp.async.cg.shared.global [%0], [%1], 16;" :: "r"(dst), "l"(src));
}
__device__ __forceinline__ void cp_commit() {
    asm volatile("cp.async.commit_group;");
}
__device__ __forceinline__ void cp_wait0() {
    asm volatile("cp.async.wait_group 0;");
}
__device__ __forceinline__ void cp_wait1() {
    asm volatile("cp.async.wait_group 1;");
}
__device__ __forceinline__ void ldm_x4(unsigned* d, unsigned addr) {
    asm volatile("ldmatrix.sync.aligned.m8n8.x4.shared.b16 {%0,%1,%2,%3}, [%4];"
                 : "=r"(d[0]), "=r"(d[1]), "=r"(d[2]), "=r"(d[3]) : "r"(addr));
}
__device__ __forceinline__ void ldm_x4_t(unsigned* d, unsigned addr) {
    asm volatile("ldmatrix.sync.aligned.m8n8.x4.trans.shared.b16 {%0,%1,%2,%3}, [%4];"
                 : "=r"(d[0]), "=r"(d[1]), "=r"(d[2]), "=r"(d[3]) : "r"(addr));
}
__device__ __forceinline__ void mma16816(float* c, const unsigned* a, const unsigned* b) {
    asm volatile("mma.sync.aligned.m16n8k16.row.col.f32.f16.f16.f32 "
                 "{%0,%1,%2,%3}, {%4,%5,%6,%7}, {%8,%9}, {%0,%1,%2,%3};"
                 : "+f"(c[0]), "+f"(c[1]), "+f"(c[2]), "+f"(c[3])
                 : "r"(a[0]), "r"(a[1]), "r"(a[2]), "r"(a[3]), "r"(b[0]), "r"(b[1]));
}

// =====================================================================
// Split-fp16 tensor-core GEMM:  C = (Ah+Al)@(Bh+Bl) + bias  (fp32 accum)
// C = Ah*Bh + Ah*Bl + Al*Bh  (Al*Bl dropped, ~2^-22)
// BM=128, BN=128, BK=32, 256 threads, warp tile 64x32, m16n8k16 mma.
// =====================================================================
#define G_AS 5120            // 128*40 halves per A tile
#define G_BS 4352            // 32*136 halves per B tile
#define G_STAGE (2*G_AS + 2*G_BS)     // halves per stage
#define G_SMEM_BYTES (2 * G_STAGE * 2)

// async-copy one k-stage of Ah/Al/Bh/Bl into stage buffer s
__device__ __forceinline__ void g_copy_stage(
    unsigned smem0, int s, int k0, int tid, int bx, int by, int N, int K,
    const __half* Ah, const __half* Al, const __half* Bh, const __half* Bl) {
    const unsigned base = smem0 + (unsigned)(s * G_STAGE) * 2u;
    #pragma unroll
    for (int i = 0; i < 2; i++) {
        int idx = tid + i * 256;           // 512 x 16B chunks per A array
        int row = idx >> 2;
        int ch  = idx & 3;
        const size_t go = (size_t)(by * 128 + row) * K + k0 + ch * 8;
        const unsigned so = (unsigned)(row * 40 + ch * 8) * 2u;
        cp16(base + so,            Ah + go);
        cp16(base + G_AS * 2 + so, Al + go);
    }
    #pragma unroll
    for (int i = 0; i < 2; i++) {
        int idx = tid + i * 256;           // 512 x 16B chunks per B array
        int row = idx >> 4;
        int ch  = idx & 15;
        const size_t go = (size_t)(k0 + row) * N + bx * 128 + ch * 8;
        const unsigned so = (unsigned)(row * 136 + ch * 8) * 2u;
        cp16(base + 2 * G_AS * 2 + so,          Bh + go);
        cp16(base + (2 * G_AS + G_BS) * 2 + so, Bl + go);
    }
}

__global__ __launch_bounds__(256)
void hgemm_split(const __half* __restrict__ Ah, const __half* __restrict__ Al,
                 const __half* __restrict__ Bh, const __half* __restrict__ Bl,
                 const float* __restrict__ bias, float* __restrict__ C,
                 int M, int N, int K) {
    extern __shared__ __half sm_h[];
    const int tid  = threadIdx.x;
    const int lane = tid & 31;
    const int warp = tid >> 5;
    const int wm = warp >> 2;            // 0..1  (m)
    const int wn = warp & 3;             // 0..3  (n)
    const int bx = blockIdx.x;
    const int by = blockIdx.y;

    const unsigned smem0 = (unsigned)__cvta_generic_to_shared(sm_h);

    float acc[4][4][4];
    #pragma unroll
    for (int i = 0; i < 4; i++) {
        #pragma unroll
        for (int j = 0; j < 4; j++) {
            acc[i][j][0] = 0.0f; acc[i][j][1] = 0.0f;
            acc[i][j][2] = 0.0f; acc[i][j][3] = 0.0f;
        }
    }

    const int nIter = K / 32;
    g_copy_stage(smem0, 0, 0, tid, bx, by, N, K, Ah, Al, Bh, Bl);
    cp_commit();

    for (int it = 0; it < nIter; it++) {
        if (it + 1 < nIter) {
            g_copy_stage(smem0, (it + 1) & 1, (it + 1) * 32, tid, bx, by, N, K,
                         Ah, Al, Bh, Bl);
            cp_commit();
            cp_wait1();
        } else {
            cp_wait0();
        }
        __syncthreads();

        const unsigned base   = smem0 + (unsigned)((it & 1) * G_STAGE) * 2u;
        const unsigned baseAh = base;
        const unsigned baseAl = base + G_AS * 2;
        const unsigned baseBh = base + 2 * G_AS * 2;
        const unsigned baseBl = base + (2 * G_AS + G_BS) * 2;

        #pragma unroll
        for (int ks = 0; ks < 2; ks++) {
            const int kk = ks * 16;
            unsigned ah[4][4], al[4][4];
            #pragma unroll
            for (int mf = 0; mf < 4; mf++) {
                const int row = wm * 64 + mf * 16 + (lane & 15);
                const int col = kk + (lane >> 4) * 8;
                const unsigned off = (unsigned)(row * 40 + col) * 2u;
                ldm_x4(ah[mf], baseAh + off);
                ldm_x4(al[mf], baseAl + off);
            }
            unsigned bh[4][2], bl[4][2];
            #pragma unroll
            for (int nh = 0; nh < 2; nh++) {
                const int row = kk + (lane & 15);
                const int col = wn * 32 + nh * 16 + (lane >> 4) * 8;
                const unsigned off = (unsigned)(row * 136 + col) * 2u;
                unsigned d[4];
                ldm_x4_t(d, baseBh + off);
                bh[nh * 2][0]     = d[0];
                bh[nh * 2][1]     = d[1];
                bh[nh * 2 + 1][0] = d[2];
                bh[nh * 2 + 1][1] = d[3];
                ldm_x4_t(d, baseBl + off);
                bl[nh * 2][0]     = d[0];
                bl[nh * 2][1]     = d[1];
                bl[nh * 2 + 1][0] = d[2];
                bl[nh * 2 + 1][1] = d[3];
            }
            #pragma unroll
            for (int mf = 0; mf < 4; mf++) {
                #pragma unroll
                for (int nf = 0; nf < 4; nf++) {
                    mma16816(acc[mf][nf], ah[mf], bh[nf]);
                    mma16816(acc[mf][nf], ah[mf], bl[nf]);
                    mma16816(acc[mf][nf], al[mf], bh[nf]);
                }
            }
        }
        __syncthreads();
    }

    // epilogue
    #pragma unroll
    for (int mf = 0; mf < 4; mf++) {
        const int row0 = by * 128 + wm * 64 + mf * 16 + (lane >> 2);
        #pragma unroll
        for (int nf = 0; nf < 4; nf++) {
            const int col = bx * 128 + wn * 32 + nf * 8 + (lane & 3) * 2;
            const float b0 = bias[col];
            const float b1 = bias[col + 1];
            float2 v0;
            float2 v1;
            v0.x = acc[mf][nf][0] + b0; v0.y = acc[mf][nf][1] + b1;
            v1.x = acc[mf][nf][2] + b0; v1.y = acc[mf][nf][3] + b1;
            *(float2*)(C + (size_t)row0 * N + col)       = v0;
            *(float2*)(C + (size_t)(row0 + 8) * N + col) = v1;
        }
    }
}

// =====================================================================
// RoPE + split into head-major Q/K/V (fp32).  Verified in R1.
// =====================================================================
__global__ __launch_bounds__(128)
void rope_split(const float* __restrict__ qkv, float* __restrict__ Q,
                float* __restrict__ K, float* __restrict__ V) {
    const int r = blockIdx.x;
    const int h = blockIdx.y;
    const int b = r >> 11;
    const int n = r & 2047;
    const int i = threadIdx.x;

    const float* base = qkv + (size_t)r * QKV_N + h * DK;
    const size_t o = ((size_t)((b << 4) + h) * SEQ + n) * DK;

    V[o + i] = base[2 * EMBED + i];

    if (i < 64) {
        const float bf_base = __bfloat162float(__float2bfloat16(10000.0f));
        const float e  = (float)i * (1.0f / 64.0f);
        const float pf = (float)pow((double)bf_base, (double)e);
        const float den = __bfloat162float(__float2bfloat16(pf));
        const float invf = __fdiv_rn(1.0f, den);
        const float theta = __bfloat162float(__float2bfloat16(invf));

        const float  freq = (float)n * theta;
        const double fd = (double)freq;
        const double kq = rint(fd * 0.15915494309189535);
        const float  rr = (float)(fd - kq * 6.283185307179586);
        const float  s = sinf(rr);
        const float  c = cosf(rr);

        const float q1 = base[i];
        const float q2 = base[i + 64];
        const float k1 = base[EMBED + i];
        const float k2 = base[EMBED + i + 64];
        Q[o + i]      = q1 * c - q2 * s;
        Q[o + i + 64] = q1 * s + q2 * c;
        K[o + i]      = k1 * c - k2 * s;
        K[o + i + 64] = k1 * s + k2 * c;
    }
}

// =====================================================================
// Causal flash attention, fp32 SIMT (verified R1), heavy-tiles-first,
// epilogue writes (hi, lo) fp16 split directly for the output GEMM.
// =====================================================================
#define FA_SMEM_FLOATS (128 * 68 + 128 * 68 + 64 * 132 + 64 * 68)
#define FA_SMEM_BYTES  (FA_SMEM_FLOATS * 4)

__global__ __launch_bounds__(256)
void flash_attn(const float* __restrict__ Q, const float* __restrict__ K,
                const float* __restrict__ V, __half* __restrict__ Oh,
                __half* __restrict__ Ol) {
    const int qt = gridDim.x - 1 - blockIdx.x;   // heaviest tile first
    const int bh = blockIdx.y;
    const int b = bh >> 4;
    const int h = bh & 15;
    const int tid = threadIdx.x;
    const int tx = tid & 15;
    const int ty = tid >> 4;

    extern __shared__ float smf[];
    float* Qs = smf;
    float* Ks = Qs + 128 * 68;
    float* Vs = Ks + 128 * 68;
    float* Ps = Vs + 64 * 132;

    const size_t hb = (size_t)bh * SEQ * DK;
    const float* Qg = Q + hb + (size_t)qt * 64 * DK;

    for (int e = tid; e < 64 * 32; e += 256) {
        const int m = e & 63;
        const int dg = (e >> 6) << 2;
        const float4 v = *(const float4*)(Qg + m * DK + dg);
        Qs[(dg + 0) * 68 + m] = v.x;
        Qs[(dg + 1) * 68 + m] = v.y;
        Qs[(dg + 2) * 68 + m] = v.z;
        Qs[(dg + 3) * 68 + m] = v.w;
    }

    float m_r[4], l_r[4], o[4][8];
    #pragma unroll
    for (int i = 0; i < 4; i++) {
        m_r[i] = -1e30f;
        l_r[i] = 0.0f;
        #pragma unroll
        for (int j = 0; j < 8; j++) o[i][j] = 0.0f;
    }
    const float scale = 0.08838834764831845f;

    for (int kt = 0; kt <= qt; kt++) {
        __syncthreads();
        const float* Kg = K + hb + (size_t)kt * 64 * DK;
        const float* Vg = V + hb + (size_t)kt * 64 * DK;
        for (int e = tid; e < 2048; e += 256) {
            const int m = e & 63;
            const int dg = (e >> 6) << 2;
            const float4 v = *(const float4*)(Kg + m * DK + dg);
            Ks[(dg + 0) * 68 + m] = v.x;
            Ks[(dg + 1) * 68 + m] = v.y;
            Ks[(dg + 2) * 68 + m] = v.z;
            Ks[(dg + 3) * 68 + m] = v.w;
        }
        for (int e = tid; e < 2048; e += 256) {
            const int m = e >> 5;
            const int dg = (e & 31) << 2;
            *(float4*)(Vs + m * 132 + dg) = *(const float4*)(Vg + m * DK + dg);
        }
        __syncthreads();

        float s[4][4];
        #pragma unroll
        for (int i = 0; i < 4; i++) {
            #pragma unroll
            for (int j = 0; j < 4; j++) s[i][j] = 0.0f;
        }

        #pragma unroll 8
        for (int k = 0; k < 128; k++) {
            const float4 qv = *(const float4*)&Qs[k * 68 + ty * 4];
            const float4 kv = *(const float4*)&Ks[k * 68 + tx * 4];
            float aq[4];
            float ak[4];
            aq[0] = qv.x; aq[1] = qv.y; aq[2] = qv.z; aq[3] = qv.w;
            ak[0] = kv.x; ak[1] = kv.y; ak[2] = kv.z; ak[3] = kv.w;
            #pragma unroll
            for (int i = 0; i < 4; i++) {
                #pragma unroll
                for (int j = 0; j < 4; j++) s[i][j] += aq[i] * ak[j];
            }
        }

        const int qbase = qt * 64 + ty * 4;
        const int kbase = kt * 64 + tx * 4;
        #pragma unroll
        for (int i = 0; i < 4; i++) {
            #pragma unroll
            for (int j = 0; j < 4; j++) {
                float sv = s[i][j] * scale;
                if (kt == qt && (kbase + j) > (qbase + i)) sv = -1e30f;
                s[i][j] = sv;
            }
        }

        float rmax[4];
        #pragma unroll
        for (int i = 0; i < 4; i++) {
            float v = fmaxf(fmaxf(s[i][0], s[i][1]), fmaxf(s[i][2], s[i][3]));
            #pragma unroll
            for (int off = 1; off < 16; off <<= 1)
                v = fmaxf(v, __shfl_xor_sync(0xffffffffu, v, off));
            rmax[i] = v;
        }

        float alpha[4];
        #pragma unroll
        for (int i = 0; i < 4; i++) {
            const float mn = fmaxf(m_r[i], rmax[i]);
            alpha[i] = __expf(m_r[i] - mn);
            m_r[i] = mn;
        }

        float rsum[4];
        #pragma unroll
        for (int i = 0; i < 4; i++) {
            float rs = 0.0f;
            #pragma unroll
            for (int j = 0; j < 4; j++) {
                const float p = __expf(s[i][j] - m_r[i]);
                s[i][j] = p;
                rs += p;
            }
            #pragma unroll
            for (int off = 1; off < 16; off <<= 1)
                rs += __shfl_xor_sync(0xffffffffu, rs, off);
            rsum[i] = rs;
        }

        #pragma unroll
        for (int i = 0; i < 4; i++) {
            l_r[i] = l_r[i] * alpha[i] + rsum[i];
            #pragma unroll
            for (int j = 0; j < 8; j++) o[i][j] *= alpha[i];
        }

        #pragma unroll
        for (int i = 0; i < 4; i++) {
            #pragma unroll
            for (int j = 0; j < 4; j++)
                Ps[(ty * 4 + i) * 68 + tx * 4 + j] = s[i][j];
        }
        __syncthreads();

        #pragma unroll 4
        for (int kv = 0; kv < 64; kv++) {
            float pv[4];
            #pragma unroll
            for (int i = 0; i < 4; i++) pv[i] = Ps[(ty * 4 + i) * 68 + kv];
            const float4 v0 = *(const float4*)&Vs[kv * 132 + tx * 8];
            const float4 v1 = *(const float4*)&Vs[kv * 132 + tx * 8 + 4];
            float av[8];
            av[0] = v0.x; av[1] = v0.y; av[2] = v0.z; av[3] = v0.w;
            av[4] = v1.x; av[5] = v1.y; av[6] = v1.z; av[7] = v1.w;
            #pragma unroll
            for (int i = 0; i < 4; i++) {
                #pragma unroll
                for (int j = 0; j < 8; j++) o[i][j] += pv[i] * av[j];
            }
        }
    }

    // epilogue: normalize + write token-major hi/lo fp16 split
    const size_t obase = ((size_t)(b * SEQ + qt * 64) * EMBED) + h * DK;
    #pragma unroll
    for (int i = 0; i < 4; i++) {
        const float inv = 1.0f / l_r[i];
        const int row = ty * 4 + i;
        __align__(16) __half hs[8];
        __align__(16) __half ls[8];
        #pragma unroll
        for (int j = 0; j < 8; j++) {
            const float val = o[i][j] * inv;
            const __half hh = __float2half_rn(val);
            hs[j] = hh;
            ls[j] = __float2half_rn(val - __half2float(hh));
        }
        const size_t off = obase + (size_t)row * EMBED + tx * 8;
        *(uint4*)(Oh + off) = *(const uint4*)hs;
        *(uint4*)(Ol + off) = *(const uint4*)ls;
    }
}

// =====================================================================
// launch
// =====================================================================
extern "C" void kernel_launch(void* const* d_in, const int* in_sizes, int n_in,
                              void* d_out, int out_size) {
    const float* x    = 0;
    const float* Wqkv = 0;
    const float* bqkv = 0;
    const float* Wo   = 0;
    const float* bo   = 0;
    for (int i = 0; i < n_in; i++) {
        if (in_sizes[i] == 8388608)  x    = (const float*)d_in[i];
        if (in_sizes[i] == 12582912) Wqkv = (const float*)d_in[i];
        if (in_sizes[i] == 6144)     bqkv = (const float*)d_in[i];
        if (in_sizes[i] == 4194304)  Wo   = (const float*)d_in[i];
        if (in_sizes[i] == 2048)     bo   = (const float*)d_in[i];
    }
    float* out = (float*)d_out;

    float* qkv;
    float* q;
    float* k;
    float* v;
    __half* xh;
    __half* xl;
    __half* wqh;
    __half* wql;
    __half* ah;
    __half* al;
    __half* woh;
    __half* wol;
    cudaGetSymbolAddress((void**)&qkv, g_qkv);
    cudaGetSymbolAddress((void**)&q,   g_q);
    cudaGetSymbolAddress((void**)&k,   g_k);
    cudaGetSymbolAddress((void**)&v,   g_v);
    cudaGetSymbolAddress((void**)&xh,  g_xh);
    cudaGetSymbolAddress((void**)&xl,  g_xl);
    cudaGetSymbolAddress((void**)&wqh, g_wqh);
    cudaGetSymbolAddress((void**)&wql, g_wql);
    cudaGetSymbolAddress((void**)&ah,  g_ah);
    cudaGetSymbolAddress((void**)&al,  g_al);
    cudaGetSymbolAddress((void**)&woh, g_woh);
    cudaGetSymbolAddress((void**)&wol, g_wol);

    cudaFuncSetAttribute(flash_attn,
                         cudaFuncAttributeMaxDynamicSharedMemorySize,
                         FA_SMEM_BYTES);
    cudaFuncSetAttribute(hgemm_split,
                         cudaFuncAttributeMaxDynamicSharedMemorySize,
                         G_SMEM_BYTES);

    const int NX  = TOKENS * EMBED;
    const int NWQ = EMBED * QKV_N;
    const int NWO = EMBED * EMBED;

    // 1) split x, W_qkv, W_o into (hi, lo) fp16
    split_kernel<<<NX / 1024, 256>>>(x, xh, xl, NX);
    split_kernel<<<NWQ / 1024, 256>>>(Wqkv, wqh, wql, NWQ);
    split_kernel<<<NWO / 1024, 256>>>(Wo, woh, wol, NWO);

    // 2) qkv = x @ W_qkv + b_qkv   (tensor cores, split fp16)
    hgemm_split<<<dim3(QKV_N / 128, TOKENS / 128), 256, G_SMEM_BYTES>>>(
        xh, xl, wqh, wql, bqkv, qkv, TOKENS, QKV_N, EMBED);

    // 3) split + RoPE
    rope_split<<<dim3(TOKENS, HEADS), 128>>>(qkv, q, k, v);

    // 4) causal flash attention (fp32), writes split fp16 output
    flash_attn<<<dim3(SEQ / 64, BATCH * HEADS), 256, FA_SMEM_BYTES>>>(
        q, k, v, ah, al);

    // 5) out = attn @ W_o + b_o   (tensor cores, split fp16)
    hgemm_split<<<dim3(EMBED / 128, TOKENS / 128), 256, G_SMEM_BYTES>>>(
        ah, al, woh, wol, bo, out, TOKENS, EMBED, EMBED);
}

// round 7
// speedup vs baseline: 2.9128x; 1.7613x over previous
#include <cuda_runtime.h>
#include <cuda_fp16.h>
#include <cuda_bf16.h>
#include <stdint.h>
#include <math.h>

// Problem constants
#define BATCH 2
#define SEQ   2048
#define EMBED 2048
#define HEADS 16
#define DK    128
#define TOKENS (BATCH * SEQ)          // 4096
#define QKV_N  (3 * EMBED)            // 6144

// ---------------- scratch (device globals; no allocation) ----------------
__device__ float g_qkv [(size_t)TOKENS * QKV_N];            // fp32 QKV

// split fp16 operands for linear GEMMs
__device__ __half g_xh [(size_t)TOKENS * EMBED];
__device__ __half g_xl [(size_t)TOKENS * EMBED];
__device__ __half g_wqh[(size_t)EMBED * QKV_N];
__device__ __half g_wql[(size_t)EMBED * QKV_N];
__device__ __half g_ah [(size_t)TOKENS * EMBED];   // attn out hi
__device__ __half g_al [(size_t)TOKENS * EMBED];   // attn out lo
__device__ __half g_woh[(size_t)EMBED * EMBED];
__device__ __half g_wol[(size_t)EMBED * EMBED];

// split fp16 Q/K/V, head-major [bh][seq][128]
#define HSZ ((size_t)BATCH * HEADS * SEQ * DK)
__device__ __half g_qh2[HSZ];
__device__ __half g_ql2[HSZ];
__device__ __half g_kh2[HSZ];
__device__ __half g_kl2[HSZ];
__device__ __half g_vh2[HSZ];
__device__ __half g_vl2[HSZ];

// =====================================================================
// split fp32 -> (hi, lo) fp16
// =====================================================================
__global__ __launch_bounds__(256)
void split_kernel(const float* __restrict__ a, __half* __restrict__ hi,
                  __half* __restrict__ lo, int n) {
    int i = (blockIdx.x * 256 + threadIdx.x) * 4;
    if (i >= n) return;
    float4 v = *(const float4*)(a + i);
    __half h0 = __float2half_rn(v.x);
    __half h1 = __float2half_rn(v.y);
    __half h2 = __float2half_rn(v.z);
    __half h3 = __float2half_rn(v.w);
    __half l0 = __float2half_rn(v.x - __half2float(h0));
    __half l1 = __float2half_rn(v.y - __half2float(h1));
    __half l2 = __float2half_rn(v.z - __half2float(h2));
    __half l3 = __float2half_rn(v.w - __half2float(h3));
    __half2* hp = (__half2*)(hi + i);
    __half2* lp = (__half2*)(lo + i);
    hp[0] = __halves2half2(h0, h1);
    hp[1] = __halves2half2(h2, h3);
    lp[0] = __halves2half2(l0, l1);
    lp[1] = __halves2half2(l2, l3);
}

// =====================================================================
// asm helpers
// =====================================================================
__device__ __forceinline__ void cp16(unsigned dst, const void* src) {
    asm volatile("cp.async.cg.shared.global [%0], [%1], 16;" :: "r"(dst), "l"(src));
}
__device__ __forceinline__ void cp_commit() {
    asm volatile("cp.async.commit_group;");
}
__device__ __forceinline__ void cp_wait0() {
    asm volatile("cp.async.wait_group 0;");
}
__device__ __forceinline__ void cp_wait1() {
    asm volatile("cp.async.wait_group 1;");
}
__device__ __forceinline__ void ldm_x4(unsigned* d, unsigned addr) {
    asm volatile("ldmatrix.sync.aligned.m8n8.x4.shared.b16 {%0,%1,%2,%3}, [%4];"
                 : "=r"(d[0]), "=r"(d[1]), "=r"(d[2]), "=r"(d[3]) : "r"(addr));
}
__device__ __forceinline__ void ldm_x4_t(unsigned* d, unsigned addr) {
    asm volatile("ldmatrix.sync.aligned.m8n8.x4.trans.shared.b16 {%0,%1,%2,%3}, [%4];"
                 : "=r"(d[0]), "=r"(d[1]), "=r"(d[2]), "=r"(d[3]) : "r"(addr));
}
__device__ __forceinline__ void mma16816(float* c, const unsigned* a, const unsigned* b) {
    asm volatile("mma.sync.aligned.m16n8k16.row.col.f32.f16.f16.f32 "
                 "{%0,%1,%2,%3}, {%4,%5,%6,%7}, {%8,%9}, {%0,%1,%2,%3};"
                 : "+f"(c[0]), "+f"(c[1]), "+f"(c[2]), "+f"(c[3])
                 : "r"(a[0]), "r"(a[1]), "r"(a[2]), "r"(a[3]), "r"(b[0]), "r"(b[1]));
}
// pack 2 fp32 into (hi half2, lo half2) as unsigned
__device__ __forceinline__ void pack2hl(float x, float y, unsigned* hi, unsigned* lo) {
    __half hx = __float2half_rn(x);
    __half hy = __float2half_rn(y);
    __half lx = __float2half_rn(x - __half2float(hx));
    __half ly = __float2half_rn(y - __half2float(hy));
    __half2 th = __halves2half2(hx, hy);
    __half2 tl = __halves2half2(lx, ly);
    *hi = *reinterpret_cast<unsigned*>(&th);
    *lo = *reinterpret_cast<unsigned*>(&tl);
}

// =====================================================================
// Split-fp16 tensor-core GEMM (verified R5)
// =====================================================================
#define G_AS 5120
#define G_BS 4352
#define G_STAGE (2*G_AS + 2*G_BS)
#define G_SMEM_BYTES (2 * G_STAGE * 2)

__device__ __forceinline__ void g_copy_stage(
    unsigned smem0, int s, int k0, int tid, int bx, int by, int N, int K,
    const __half* Ah, const __half* Al, const __half* Bh, const __half* Bl) {
    const unsigned base = smem0 + (unsigned)(s * G_STAGE) * 2u;
    #pragma unroll
    for (int i = 0; i < 2; i++) {
        int idx = tid + i * 256;
        int row = idx >> 2;
        int ch  = idx & 3;
        const size_t go = (size_t)(by * 128 + row) * K + k0 + ch * 8;
        const unsigned so = (unsigned)(row * 40 + ch * 8) * 2u;
        cp16(base + so,            Ah + go);
        cp16(base + G_AS * 2 + so, Al + go);
    }
    #pragma unroll
    for (int i = 0; i < 2; i++) {
        int idx = tid + i * 256;
        int row = idx >> 4;
        int ch  = idx & 15;
        const size_t go = (size_t)(k0 + row) * N + bx * 128 + ch * 8;
        const unsigned so = (unsigned)(row * 136 + ch * 8) * 2u;
        cp16(base + 2 * G_AS * 2 + so,          Bh + go);
        cp16(base + (2 * G_AS + G_BS) * 2 + so, Bl + go);
    }
}

__global__ __launch_bounds__(256)
void hgemm_split(const __half* __restrict__ Ah, const __half* __restrict__ Al,
                 const __half* __restrict__ Bh, const __half* __restrict__ Bl,
                 const float* __restrict__ bias, float* __restrict__ C,
                 int M, int N, int K) {
    extern __shared__ __half sm_h[];
    const int tid  = threadIdx.x;
    const int lane = tid & 31;
    const int warp = tid >> 5;
    const int wm = warp >> 2;
    const int wn = warp & 3;
    const int bx = blockIdx.x;
    const int by = blockIdx.y;

    const unsigned smem0 = (unsigned)__cvta_generic_to_shared(sm_h);

    float acc[4][4][4];
    #pragma unroll
    for (int i = 0; i < 4; i++) {
        #pragma unroll
        for (int j = 0; j < 4; j++) {
            acc[i][j][0] = 0.0f; acc[i][j][1] = 0.0f;
            acc[i][j][2] = 0.0f; acc[i][j][3] = 0.0f;
        }
    }

    const int nIter = K / 32;
    g_copy_stage(smem0, 0, 0, tid, bx, by, N, K, Ah, Al, Bh, Bl);
    cp_commit();

    for (int it = 0; it < nIter; it++) {
        if (it + 1 < nIter) {
            g_copy_stage(smem0, (it + 1) & 1, (it + 1) * 32, tid, bx, by, N, K,
                         Ah, Al, Bh, Bl);
            cp_commit();
            cp_wait1();
        } else {
            cp_wait0();
        }
        __syncthreads();

        const unsigned base   = smem0 + (unsigned)((it & 1) * G_STAGE) * 2u;
        const unsigned baseAh = base;
        const unsigned baseAl = base + G_AS * 2;
        const unsigned baseBh = base + 2 * G_AS * 2;
        const unsigned baseBl = base + (2 * G_AS + G_BS) * 2;

        #pragma unroll
        for (int ks = 0; ks < 2; ks++) {
            const int kk = ks * 16;
            unsigned ah[4][4], al[4][4];
            #pragma unroll
            for (int mf = 0; mf < 4; mf++) {
                const int row = wm * 64 + mf * 16 + (lane & 15);
                const int col = kk + (lane >> 4) * 8;
                const unsigned off = (unsigned)(row * 40 + col) * 2u;
                ldm_x4(ah[mf], baseAh + off);
                ldm_x4(al[mf], baseAl + off);
            }
            unsigned bh[4][2], bl[4][2];
            #pragma unroll
            for (int nh = 0; nh < 2; nh++) {
                const int row = kk + (lane & 15);
                const int col = wn * 32 + nh * 16 + (lane >> 4) * 8;
                const unsigned off = (unsigned)(row * 136 + col) * 2u;
                unsigned d[4];
                ldm_x4_t(d, baseBh + off);
                bh[nh * 2][0]     = d[0];
                bh[nh * 2][1]     = d[1];
                bh[nh * 2 + 1][0] = d[2];
                bh[nh * 2 + 1][1] = d[3];
                ldm_x4_t(d, baseBl + off);
                bl[nh * 2][0]     = d[0];
                bl[nh * 2][1]     = d[1];
                bl[nh * 2 + 1][0] = d[2];
                bl[nh * 2 + 1][1] = d[3];
            }
            #pragma unroll
            for (int mf = 0; mf < 4; mf++) {
                #pragma unroll
                for (int nf = 0; nf < 4; nf++) {
                    mma16816(acc[mf][nf], ah[mf], bh[nf]);
                    mma16816(acc[mf][nf], ah[mf], bl[nf]);
                    mma16816(acc[mf][nf], al[mf], bh[nf]);
                }
            }
        }
        __syncthreads();
    }

    #pragma unroll
    for (int mf = 0; mf < 4; mf++) {
        const int row0 = by * 128 + wm * 64 + mf * 16 + (lane >> 2);
        #pragma unroll
        for (int nf = 0; nf < 4; nf++) {
            const int col = bx * 128 + wn * 32 + nf * 8 + (lane & 3) * 2;
            const float b0 = bias[col];
            const float b1 = bias[col + 1];
            float2 v0;
            float2 v1;
            v0.x = acc[mf][nf][0] + b0; v0.y = acc[mf][nf][1] + b1;
            v1.x = acc[mf][nf][2] + b0; v1.y = acc[mf][nf][3] + b1;
            *(float2*)(C + (size_t)row0 * N + col)       = v0;
            *(float2*)(C + (size_t)(row0 + 8) * N + col) = v1;
        }
    }
}

// =====================================================================
// RoPE + split into head-major (hi, lo) fp16 Q/K/V.
// =====================================================================
__global__ __launch_bounds__(128)
void rope_split(const float* __restrict__ qkv,
                __half* __restrict__ Qh, __half* __restrict__ Ql,
                __half* __restrict__ Kh, __half* __restrict__ Kl,
                __half* __restrict__ Vh, __half* __restrict__ Vl) {
    const int r = blockIdx.x;
    const int h = blockIdx.y;
    const int b = r >> 11;
    const int n = r & 2047;
    const int i = threadIdx.x;

    const float* base = qkv + (size_t)r * QKV_N + h * DK;
    const size_t o = ((size_t)((b << 4) + h) * SEQ + n) * DK;

    {
        const float vv = base[2 * EMBED + i];
        const __half vh = __float2half_rn(vv);
        Vh[o + i] = vh;
        Vl[o + i] = __float2half_rn(vv - __half2float(vh));
    }

    if (i < 64) {
        const float bf_base = __bfloat162float(__float2bfloat16(10000.0f));
        const float e  = (float)i * (1.0f / 64.0f);
        const float pf = (float)pow((double)bf_base, (double)e);
        const float den = __bfloat162float(__float2bfloat16(pf));
        const float invf = __fdiv_rn(1.0f, den);
        const float theta = __bfloat162float(__float2bfloat16(invf));

        const float  freq = (float)n * theta;
        const double fd = (double)freq;
        const double kq = rint(fd * 0.15915494309189535);
        const float  rr = (float)(fd - kq * 6.283185307179586);
        const float  s = sinf(rr);
        const float  c = cosf(rr);

        const float q1 = base[i];
        const float q2 = base[i + 64];
        const float k1 = base[EMBED + i];
        const float k2 = base[EMBED + i + 64];
        const float qa = q1 * c - q2 * s;
        const float qb = q1 * s + q2 * c;
        const float ka = k1 * c - k2 * s;
        const float kb = k1 * s + k2 * c;

        const __half qah = __float2half_rn(qa);
        const __half qbh = __float2half_rn(qb);
        const __half kah = __float2half_rn(ka);
        const __half kbh = __float2half_rn(kb);
        Qh[o + i]      = qah;
        Qh[o + i + 64] = qbh;
        Kh[o + i]      = kah;
        Kh[o + i + 64] = kbh;
        Ql[o + i]      = __float2half_rn(qa - __half2float(qah));
        Ql[o + i + 64] = __float2half_rn(qb - __half2float(qbh));
        Kl[o + i]      = __float2half_rn(ka - __half2float(kah));
        Kl[o + i + 64] = __float2half_rn(kb - __half2float(kbh));
    }
}

// =====================================================================
// MMA flash attention (split fp16, fp32 softmax).
// BM=128 queries, 64-key tiles, 8 warps x 16 rows, d=128.
// smem: Q (hi,lo) resident + 2-stage K/V (hi,lo), padded stride 136.
// Unroll caps keep ptxas code size bounded.
// =====================================================================
#define FQ_H   0
#define FQ_L   17408
#define FSTAGE 34816
#define FSTRIDE 34816
#define FKH 0
#define FKL 8704
#define FVH 17408
#define FVL 26112
#define FA_SMEM_BYTES ((FSTAGE + 2 * FSTRIDE) * 2)   // 208896

__device__ __forceinline__ void fa_load_kv(
    unsigned smem0, int s, int kb, int tid, size_t hb,
    const __half* Kh, const __half* Kl, const __half* Vh, const __half* Vl) {
    const unsigned base = smem0 + (unsigned)(FSTAGE + s * FSTRIDE) * 2u;
    #pragma unroll
    for (int i = 0; i < 16; i++) {
        const int idx = tid + i * 256;       // 0..4095
        const int a   = idx >> 10;           // 0..3
        const int row = (idx >> 4) & 63;
        const int ch  = idx & 15;
        const __half* src = (a == 0) ? Kh : (a == 1) ? Kl : (a == 2) ? Vh : Vl;
        src += hb + (size_t)(kb + row) * DK + ch * 8;
        const unsigned dst = base + (unsigned)(a * 8704 + row * 136 + ch * 8) * 2u;
        cp16(dst, src);
    }
}

__global__ __launch_bounds__(256)
void flash_attn_mma(const __half* __restrict__ Qh_g, const __half* __restrict__ Ql_g,
                    const __half* __restrict__ Kh_g, const __half* __restrict__ Kl_g,
                    const __half* __restrict__ Vh_g, const __half* __restrict__ Vl_g,
                    __half* __restrict__ Oh, __half* __restrict__ Ol) {
    const int qt = gridDim.x - 1 - blockIdx.x;   // heavy tiles first
    const int bh = blockIdx.y;
    const int bIdx = bh >> 4;
    const int h = bh & 15;
    const int tid = threadIdx.x;
    const int lane = tid & 31;
    const int warp = tid >> 5;

    extern __shared__ __half fsm[];
    const unsigned smem0 = (unsigned)__cvta_generic_to_shared(fsm);

    const size_t hb = (size_t)bh * SEQ * DK;
    const int qb = qt * 128;
    const int mb = warp * 16;
    const int ktmax = 2 * qt + 1;

    // ---- load Q (hi, lo) into smem
    #pragma unroll
    for (int i = 0; i < 16; i++) {
        const int idx = tid + i * 256;       // 0..4095
        const int a   = idx >> 11;           // 0..1
        const int row = (idx >> 4) & 127;
        const int ch  = idx & 15;
        const __half* src = (a == 0) ? Qh_g : Ql_g;
        src += hb + (size_t)(qb + row) * DK + ch * 8;
        const unsigned dst = smem0 +
            (unsigned)((a == 0 ? FQ_H : FQ_L) + row * 136 + ch * 8) * 2u;
        cp16(dst, src);
    }
    cp_commit();
    fa_load_kv(smem0, 0, 0, tid, hb, Kh_g, Kl_g, Vh_g, Vl_g);
    cp_commit();
    cp_wait0();
    __syncthreads();

    float o[16][4];
    #pragma unroll
    for (int i = 0; i < 16; i++) {
        o[i][0] = 0.0f; o[i][1] = 0.0f; o[i][2] = 0.0f; o[i][3] = 0.0f;
    }
    float m0 = -1e30f, m1 = -1e30f, l0 = 0.0f, l1 = 0.0f;
    const float sc = 0.08838834764831845f;   // 1/sqrt(128)

    const unsigned sQH = smem0 + FQ_H * 2;
    const unsigned sQL = smem0 + FQ_L * 2;

    for (int kt = 0; kt <= ktmax; kt++) {
        if (kt < ktmax) {
            fa_load_kv(smem0, (kt + 1) & 1, (kt + 1) * 64, tid, hb,
                       Kh_g, Kl_g, Vh_g, Vl_g);
            cp_commit();
        }
        const unsigned stg = smem0 + (unsigned)(FSTAGE + (kt & 1) * FSTRIDE) * 2u;
        const unsigned sKH = stg + FKH * 2;
        const unsigned sKL = stg + FKL * 2;
        const unsigned sVH = stg + FVH * 2;
        const unsigned sVL = stg + FVL * 2;

        // ---- S = Q K^T (split x3)
        float s[8][4];
        #pragma unroll
        for (int j = 0; j < 8; j++) {
            s[j][0] = 0.0f; s[j][1] = 0.0f; s[j][2] = 0.0f; s[j][3] = 0.0f;
        }
        #pragma unroll 2
        for (int ks = 0; ks < 8; ks++) {
            const int kk = ks * 16;
            unsigned qfh[4], qfl[4];
            const unsigned qoff =
                (unsigned)((mb + (lane & 15)) * 136 + kk + (lane >> 4) * 8) * 2u;
            ldm_x4(qfh, sQH + qoff);
            ldm_x4(qfl, sQL + qoff);
            const int krow = ((lane >> 4) & 1) * 8 + (lane & 7);
            const int kcol = kk + ((lane >> 3) & 1) * 8;
            #pragma unroll
            for (int nb4 = 0; nb4 < 4; nb4++) {
                const unsigned koff =
                    (unsigned)((nb4 * 16 + krow) * 136 + kcol) * 2u;
                unsigned kfh[4], kfl[4];
                ldm_x4(kfh, sKH + koff);
                ldm_x4(kfl, sKL + koff);
                mma16816(s[2 * nb4],     qfh, kfh);
                mma16816(s[2 * nb4],     qfh, kfl);
                mma16816(s[2 * nb4],     qfl, kfh);
                mma16816(s[2 * nb4 + 1], qfh, kfh + 2);
                mma16816(s[2 * nb4 + 1], qfh, kfl + 2);
                mma16816(s[2 * nb4 + 1], qfl, kfh + 2);
            }
        }

        // ---- scale + causal mask
        if (kt >= 2 * qt) {
            const int row0 = qb + mb + (lane >> 2);
            const int row1 = row0 + 8;
            const int kb = kt * 64;
            #pragma unroll
            for (int j = 0; j < 8; j++) {
                const int c0 = kb + 8 * j + 2 * (lane & 3);
                s[j][0] = (c0     > row0) ? -1e30f : s[j][0] * sc;
                s[j][1] = (c0 + 1 > row0) ? -1e30f : s[j][1] * sc;
                s[j][2] = (c0     > row1) ? -1e30f : s[j][2] * sc;
                s[j][3] = (c0 + 1 > row1) ? -1e30f : s[j][3] * sc;
            }
        } else {
            #pragma unroll
            for (int j = 0; j < 8; j++) {
                s[j][0] *= sc; s[j][1] *= sc; s[j][2] *= sc; s[j][3] *= sc;
            }
        }

        // ---- row max (rows live in 4-lane groups)
        float rm0 = -1e30f, rm1 = -1e30f;
        #pragma unroll
        for (int j = 0; j < 8; j++) {
            rm0 = fmaxf(rm0, fmaxf(s[j][0], s[j][1]));
            rm1 = fmaxf(rm1, fmaxf(s[j][2], s[j][3]));
        }
        rm0 = fmaxf(rm0, __shfl_xor_sync(0xffffffffu, rm0, 1));
        rm0 = fmaxf(rm0, __shfl_xor_sync(0xffffffffu, rm0, 2));
        rm1 = fmaxf(rm1, __shfl_xor_sync(0xffffffffu, rm1, 1));
        rm1 = fmaxf(rm1, __shfl_xor_sync(0xffffffffu, rm1, 2));

        const float mn0 = fmaxf(m0, rm0);
        const float mn1 = fmaxf(m1, rm1);
        const float a0 = __expf(m0 - mn0);
        const float a1 = __expf(m1 - mn1);
        m0 = mn0; m1 = mn1;

        float sum0 = 0.0f, sum1 = 0.0f;
        #pragma unroll
        for (int j = 0; j < 8; j++) {
            const float p0 = __expf(s[j][0] - m0);
            const float p1 = __expf(s[j][1] - m0);
            const float p2 = __expf(s[j][2] - m1);
            const float p3 = __expf(s[j][3] - m1);
            s[j][0] = p0; s[j][1] = p1; s[j][2] = p2; s[j][3] = p3;
            sum0 += p0 + p1;
            sum1 += p2 + p3;
        }
        sum0 += __shfl_xor_sync(0xffffffffu, sum0, 1);
        sum0 += __shfl_xor_sync(0xffffffffu, sum0, 2);
        sum1 += __shfl_xor_sync(0xffffffffu, sum1, 1);
        sum1 += __shfl_xor_sync(0xffffffffu, sum1, 2);
        l0 = l0 * a0 + sum0;
        l1 = l1 * a1 + sum1;

        #pragma unroll
        for (int jj = 0; jj < 16; jj++) {
            o[jj][0] *= a0; o[jj][1] *= a0; o[jj][2] *= a1; o[jj][3] *= a1;
        }

        // ---- pack P into a-fragments (hi, lo)
        unsigned pah[4][4], pal[4][4];
        #pragma unroll
        for (int t = 0; t < 4; t++) {
            pack2hl(s[2 * t][0],     s[2 * t][1],     &pah[t][0], &pal[t][0]);
            pack2hl(s[2 * t][2],     s[2 * t][3],     &pah[t][1], &pal[t][1]);
            pack2hl(s[2 * t + 1][0], s[2 * t + 1][1], &pah[t][2], &pal[t][2]);
            pack2hl(s[2 * t + 1][2], s[2 * t + 1][3], &pah[t][3], &pal[t][3]);
        }

        // ---- O += P V (split x3)
        #pragma unroll 1
        for (int t = 0; t < 4; t++) {
            const int vrow = t * 16 + (lane & 15);
            const int vco = (lane >> 4) * 8;
            #pragma unroll
            for (int db4 = 0; db4 < 8; db4++) {
                const unsigned voff =
                    (unsigned)(vrow * 136 + db4 * 16 + vco) * 2u;
                unsigned vfh[4], vfl[4];
                ldm_x4_t(vfh, sVH + voff);
                ldm_x4_t(vfl, sVL + voff);
                mma16816(o[2 * db4],     pah[t], vfh);
                mma16816(o[2 * db4],     pah[t], vfl);
                mma16816(o[2 * db4],     pal[t], vfh);
                mma16816(o[2 * db4 + 1], pah[t], vfh + 2);
                mma16816(o[2 * db4 + 1], pah[t], vfl + 2);
                mma16816(o[2 * db4 + 1], pal[t], vfh + 2);
            }
        }

        if (kt < ktmax) cp_wait0();
        __syncthreads();
    }

    // ---- epilogue: normalize, split, write token-major
    const float inv0 = 1.0f / l0;
    const float inv1 = 1.0f / l1;
    const int row0 = qb + mb + (lane >> 2);
    const size_t tok0 = (size_t)bIdx * SEQ + row0;
    const size_t tok1 = tok0 + 8;
    const int colbase = h * DK + 2 * (lane & 3);
    #pragma unroll
    for (int jj = 0; jj < 16; jj++) {
        const int col = colbase + 8 * jj;
        unsigned hh0, ll0, hh1, ll1;
        pack2hl(o[jj][0] * inv0, o[jj][1] * inv0, &hh0, &ll0);
        pack2hl(o[jj][2] * inv1, o[jj][3] * inv1, &hh1, &ll1);
        *(unsigned*)(Oh + tok0 * EMBED + col) = hh0;
        *(unsigned*)(Ol + tok0 * EMBED + col) = ll0;
        *(unsigned*)(Oh + tok1 * EMBED + col) = hh1;
        *(unsigned*)(Ol + tok1 * EMBED + col) = ll1;
    }
}

// =====================================================================
// launch
// =====================================================================
extern "C" void kernel_launch(void* const* d_in, const int* in_sizes, int n_in,
                              void* d_out, int out_size) {
    const float* x    = 0;
    const float* Wqkv = 0;
    const float* bqkv = 0;
    const float* Wo   = 0;
    const float* bo   = 0;
    for (int i = 0; i < n_in; i++) {
        if (in_sizes[i] == 8388608)  x    = (const float*)d_in[i];
        if (in_sizes[i] == 12582912) Wqkv = (const float*)d_in[i];
        if (in_sizes[i] == 6144)     bqkv = (const float*)d_in[i];
        if (in_sizes[i] == 4194304)  Wo   = (const float*)d_in[i];
        if (in_sizes[i] == 2048)     bo   = (const float*)d_in[i];
    }
    float* out = (float*)d_out;

    float* qkv;
    __half* xh;  __half* xl;
    __half* wqh; __half* wql;
    __half* ah;  __half* al;
    __half* woh; __half* wol;
    __half* qh;  __half* ql;
    __half* kh;  __half* kl;
    __half* vh;  __half* vl;
    cudaGetSymbolAddress((void**)&qkv, g_qkv);
    cudaGetSymbolAddress((void**)&xh,  g_xh);
    cudaGetSymbolAddress((void**)&xl,  g_xl);
    cudaGetSymbolAddress((void**)&wqh, g_wqh);
    cudaGetSymbolAddress((void**)&wql, g_wql);
    cudaGetSymbolAddress((void**)&ah,  g_ah);
    cudaGetSymbolAddress((void**)&al,  g_al);
    cudaGetSymbolAddress((void**)&woh, g_woh);
    cudaGetSymbolAddress((void**)&wol, g_wol);
    cudaGetSymbolAddress((void**)&qh,  g_qh2);
    cudaGetSymbolAddress((void**)&ql,  g_ql2);
    cudaGetSymbolAddress((void**)&kh,  g_kh2);
    cudaGetSymbolAddress((void**)&kl,  g_kl2);
    cudaGetSymbolAddress((void**)&vh,  g_vh2);
    cudaGetSymbolAddress((void**)&vl,  g_vl2);

    cudaFuncSetAttribute(hgemm_split,
                         cudaFuncAttributeMaxDynamicSharedMemorySize,
                         G_SMEM_BYTES);
    cudaFuncSetAttribute(flash_attn_mma,
                         cudaFuncAttributeMaxDynamicSharedMemorySize,
                         FA_SMEM_BYTES);

    const int NX  = TOKENS * EMBED;
    const int NWQ = EMBED * QKV_N;
    const int NWO = EMBED * EMBED;

    // 1) split inputs
    split_kernel<<<NX / 1024, 256>>>(x, xh, xl, NX);
    split_kernel<<<NWQ / 1024, 256>>>(Wqkv, wqh, wql, NWQ);
    split_kernel<<<NWO / 1024, 256>>>(Wo, woh, wol, NWO);

    // 2) qkv = x @ W_qkv + b_qkv
    hgemm_split<<<dim3(QKV_N / 128, TOKENS / 128), 256, G_SMEM_BYTES>>>(
        xh, xl, wqh, wql, bqkv, qkv, TOKENS, QKV_N, EMBED);

    // 3) RoPE + split to head-major fp16 pairs
    rope_split<<<dim3(TOKENS, HEADS), 128>>>(qkv, qh, ql, kh, kl, vh, vl);

    // 4) MMA flash attention -> split fp16 attn output
    flash_attn_mma<<<dim3(SEQ / 128, BATCH * HEADS), 256, FA_SMEM_BYTES>>>(
        qh, ql, kh, kl, vh, vl, ah, al);

    // 5) out = attn @ W_o + b_o
    hgemm_split<<<dim3(EMBED / 128, TOKENS / 128), 256, G_SMEM_BYTES>>>(
        ah, al, woh, wol, bo, out, TOKENS, EMBED, EMBED);
}

// round 8
// speedup vs baseline: 3.7671x; 1.2933x over previous
#include <cuda_runtime.h>
#include <cuda_fp16.h>
#include <cuda_bf16.h>
#include <stdint.h>
#include <math.h>

// Problem constants
#define BATCH 2
#define SEQ   2048
#define EMBED 2048
#define HEADS 16
#define DK    128
#define TOKENS (BATCH * SEQ)          // 4096
#define QKV_N  (3 * EMBED)            // 6144

// ---------------- scratch (device globals; no allocation) ----------------
__device__ float g_qkv [(size_t)TOKENS * QKV_N];            // fp32 QKV

// fp16 operands for linear GEMMs (A-side hi only; B-side hi+lo)
__device__ __half g_xh [(size_t)TOKENS * EMBED];
__device__ __half g_wqh[(size_t)EMBED * QKV_N];
__device__ __half g_wql[(size_t)EMBED * QKV_N];
__device__ __half g_ah [(size_t)TOKENS * EMBED];   // attn out hi (from flash_attn)
__device__ __half g_woh[(size_t)EMBED * EMBED];
__device__ __half g_wol[(size_t)EMBED * EMBED];

// split fp16 Q/K/V, head-major [bh][seq][128]  (FA keeps 3-term precision)
#define HSZ ((size_t)BATCH * HEADS * SEQ * DK)
__device__ __half g_qh2[HSZ];
__device__ __half g_ql2[HSZ];
__device__ __half g_kh2[HSZ];
__device__ __half g_kl2[HSZ];
__device__ __half g_vh2[HSZ];
__device__ __half g_vl2[HSZ];

// =====================================================================
// split fp32 -> (hi, lo) fp16   (used for weights)
// =====================================================================
__global__ __launch_bounds__(256)
void split_kernel(const float* __restrict__ a, __half* __restrict__ hi,
                  __half* __restrict__ lo, int n) {
    int i = (blockIdx.x * 256 + threadIdx.x) * 4;
    if (i >= n) return;
    float4 v = *(const float4*)(a + i);
    __half h0 = __float2half_rn(v.x);
    __half h1 = __float2half_rn(v.y);
    __half h2 = __float2half_rn(v.z);
    __half h3 = __float2half_rn(v.w);
    __half l0 = __float2half_rn(v.x - __half2float(h0));
    __half l1 = __float2half_rn(v.y - __half2float(h1));
    __half l2 = __float2half_rn(v.z - __half2float(h2));
    __half l3 = __float2half_rn(v.w - __half2float(h3));
    __half2* hp = (__half2*)(hi + i);
    __half2* lp = (__half2*)(lo + i);
    hp[0] = __halves2half2(h0, h1);
    hp[1] = __halves2half2(h2, h3);
    lp[0] = __halves2half2(l0, l1);
    lp[1] = __halves2half2(l2, l3);
}

// hi-only variant (activation side of 2-term GEMM)
__global__ __launch_bounds__(256)
void split_hi_kernel(const float* __restrict__ a, __half* __restrict__ hi, int n) {
    int i = (blockIdx.x * 256 + threadIdx.x) * 4;
    if (i >= n) return;
    float4 v = *(const float4*)(a + i);
    __half2* hp = (__half2*)(hi + i);
    hp[0] = __halves2half2(__float2half_rn(v.x), __float2half_rn(v.y));
    hp[1] = __halves2half2(__float2half_rn(v.z), __float2half_rn(v.w));
}

// =====================================================================
// asm helpers
// =====================================================================
__device__ __forceinline__ void cp16(unsigned dst, const void* src) {
    asm volatile("cp.async.cg.shared.global [%0], [%1], 16;" :: "r"(dst), "l"(src));
}
__device__ __forceinline__ void cp_commit() {
    asm volatile("cp.async.commit_group;");
}
__device__ __forceinline__ void cp_wait0() {
    asm volatile("cp.async.wait_group 0;");
}
__device__ __forceinline__ void cp_wait1() {
    asm volatile("cp.async.wait_group 1;");
}
__device__ __forceinline__ void ldm_x4(unsigned* d, unsigned addr) {
    asm volatile("ldmatrix.sync.aligned.m8n8.x4.shared.b16 {%0,%1,%2,%3}, [%4];"
                 : "=r"(d[0]), "=r"(d[1]), "=r"(d[2]), "=r"(d[3]) : "r"(addr));
}
__device__ __forceinline__ void ldm_x4_t(unsigned* d, unsigned addr) {
    asm volatile("ldmatrix.sync.aligned.m8n8.x4.trans.shared.b16 {%0,%1,%2,%3}, [%4];"
                 : "=r"(d[0]), "=r"(d[1]), "=r"(d[2]), "=r"(d[3]) : "r"(addr));
}
__device__ __forceinline__ void mma16816(float* c, const unsigned* a, const unsigned* b) {
    asm volatile("mma.sync.aligned.m16n8k16.row.col.f32.f16.f16.f32 "
                 "{%0,%1,%2,%3}, {%4,%5,%6,%7}, {%8,%9}, {%0,%1,%2,%3};"
                 : "+f"(c[0]), "+f"(c[1]), "+f"(c[2]), "+f"(c[3])
                 : "r"(a[0]), "r"(a[1]), "r"(a[2]), "r"(a[3]), "r"(b[0]), "r"(b[1]));
}
// pack 2 fp32 into (hi half2, lo half2) as unsigned
__device__ __forceinline__ void pack2hl(float x, float y, unsigned* hi, unsigned* lo) {
    __half hx = __float2half_rn(x);
    __half hy = __float2half_rn(y);
    __half lx = __float2half_rn(x - __half2float(hx));
    __half ly = __float2half_rn(y - __half2float(hy));
    __half2 th = __halves2half2(hx, hy);
    __half2 tl = __halves2half2(lx, ly);
    *hi = *reinterpret_cast<unsigned*>(&th);
    *lo = *reinterpret_cast<unsigned*>(&tl);
}
__device__ __forceinline__ unsigned pack2h(float x, float y) {
    __half2 t = __halves2half2(__float2half_rn(x), __float2half_rn(y));
    return *reinterpret_cast<unsigned*>(&t);
}

// =====================================================================
// 2-term split GEMM:  C = Ah @ (Bh + Bl) + bias   (fp32 accum)
// A-side error ~2^-12 relative (random-sign averaged ~1.4e-4).
// BM=128, BN=128, BK=32, 256 threads, warp tile 64x32, m16n8k16.
// =====================================================================
#define G2_AS 5120                       // 128*40 halves (Ah)
#define G2_BS 4352                       // 32*136 halves (per B array)
#define G2_STAGE (G2_AS + 2*G2_BS)       // 13824 halves per stage
#define G2_SMEM_BYTES (2 * G2_STAGE * 2) // 55296 B

__device__ __forceinline__ void g2_copy_stage(
    unsigned smem0, int s, int k0, int tid, int bx, int by, int N, int K,
    const __half* Ah, const __half* Bh, const __half* Bl) {
    const unsigned base = smem0 + (unsigned)(s * G2_STAGE) * 2u;
    #pragma unroll
    for (int i = 0; i < 2; i++) {
        int idx = tid + i * 256;           // 512 x 16B chunks (A)
        int row = idx >> 2;
        int ch  = idx & 3;
        const size_t go = (size_t)(by * 128 + row) * K + k0 + ch * 8;
        const unsigned so = (unsigned)(row * 40 + ch * 8) * 2u;
        cp16(base + so, Ah + go);
    }
    #pragma unroll
    for (int i = 0; i < 2; i++) {
        int idx = tid + i * 256;           // 512 x 16B chunks per B array
        int row = idx >> 4;
        int ch  = idx & 15;
        const size_t go = (size_t)(k0 + row) * N + bx * 128 + ch * 8;
        const unsigned so = (unsigned)(row * 136 + ch * 8) * 2u;
        cp16(base + G2_AS * 2 + so,             Bh + go);
        cp16(base + (G2_AS + G2_BS) * 2 + so,   Bl + go);
    }
}

__global__ __launch_bounds__(256)
void hgemm2(const __half* __restrict__ Ah,
            const __half* __restrict__ Bh, const __half* __restrict__ Bl,
            const float* __restrict__ bias, float* __restrict__ C,
            int M, int N, int K) {
    extern __shared__ __half sm_h[];
    const int tid  = threadIdx.x;
    const int lane = tid & 31;
    const int warp = tid >> 5;
    const int wm = warp >> 2;
    const int wn = warp & 3;
    const int bx = blockIdx.x;
    const int by = blockIdx.y;

    const unsigned smem0 = (unsigned)__cvta_generic_to_shared(sm_h);

    float acc[4][4][4];
    #pragma unroll
    for (int i = 0; i < 4; i++) {
        #pragma unroll
        for (int j = 0; j < 4; j++) {
            acc[i][j][0] = 0.0f; acc[i][j][1] = 0.0f;
            acc[i][j][2] = 0.0f; acc[i][j][3] = 0.0f;
        }
    }

    const int nIter = K / 32;
    g2_copy_stage(smem0, 0, 0, tid, bx, by, N, K, Ah, Bh, Bl);
    cp_commit();

    for (int it = 0; it < nIter; it++) {
        if (it + 1 < nIter) {
            g2_copy_stage(smem0, (it + 1) & 1, (it + 1) * 32, tid, bx, by, N, K,
                          Ah, Bh, Bl);
            cp_commit();
            cp_wait1();
        } else {
            cp_wait0();
        }
        __syncthreads();

        const unsigned base   = smem0 + (unsigned)((it & 1) * G2_STAGE) * 2u;
        const unsigned baseA  = base;
        const unsigned baseBh = base + G2_AS * 2;
        const unsigned baseBl = base + (G2_AS + G2_BS) * 2;

        #pragma unroll
        for (int ks = 0; ks < 2; ks++) {
            const int kk = ks * 16;
            unsigned af[4][4];
            #pragma unroll
            for (int mf = 0; mf < 4; mf++) {
                const int row = wm * 64 + mf * 16 + (lane & 15);
                const int col = kk + (lane >> 4) * 8;
                const unsigned off = (unsigned)(row * 40 + col) * 2u;
                ldm_x4(af[mf], baseA + off);
            }
            unsigned bh[4][2], bl[4][2];
            #pragma unroll
            for (int nh = 0; nh < 2; nh++) {
                const int row = kk + (lane & 15);
                const int col = wn * 32 + nh * 16 + (lane >> 4) * 8;
                const unsigned off = (unsigned)(row * 136 + col) * 2u;
                unsigned d[4];
                ldm_x4_t(d, baseBh + off);
                bh[nh * 2][0]     = d[0];
                bh[nh * 2][1]     = d[1];
                bh[nh * 2 + 1][0] = d[2];
                bh[nh * 2 + 1][1] = d[3];
                ldm_x4_t(d, baseBl + off);
                bl[nh * 2][0]     = d[0];
                bl[nh * 2][1]     = d[1];
                bl[nh * 2 + 1][0] = d[2];
                bl[nh * 2 + 1][1] = d[3];
            }
            #pragma unroll
            for (int mf = 0; mf < 4; mf++) {
                #pragma unroll
                for (int nf = 0; nf < 4; nf++) {
                    mma16816(acc[mf][nf], af[mf], bh[nf]);
                    mma16816(acc[mf][nf], af[mf], bl[nf]);
                }
            }
        }
        __syncthreads();
    }

    #pragma unroll
    for (int mf = 0; mf < 4; mf++) {
        const int row0 = by * 128 + wm * 64 + mf * 16 + (lane >> 2);
        #pragma unroll
        for (int nf = 0; nf < 4; nf++) {
            const int col = bx * 128 + wn * 32 + nf * 8 + (lane & 3) * 2;
            const float b0 = bias[col];
            const float b1 = bias[col + 1];
            float2 v0;
            float2 v1;
            v0.x = acc[mf][nf][0] + b0; v0.y = acc[mf][nf][1] + b1;
            v1.x = acc[mf][nf][2] + b0; v1.y = acc[mf][nf][3] + b1;
            *(float2*)(C + (size_t)row0 * N + col)       = v0;
            *(float2*)(C + (size_t)(row0 + 8) * N + col) = v1;
        }
    }
}

// =====================================================================
// RoPE + split into head-major (hi, lo) fp16 Q/K/V.
// =====================================================================
__global__ __launch_bounds__(128)
void rope_split(const float* __restrict__ qkv,
                __half* __restrict__ Qh, __half* __restrict__ Ql,
                __half* __restrict__ Kh, __half* __restrict__ Kl,
                __half* __restrict__ Vh, __half* __restrict__ Vl) {
    const int r = blockIdx.x;
    const int h = blockIdx.y;
    const int b = r >> 11;
    const int n = r & 2047;
    const int i = threadIdx.x;

    const float* base = qkv + (size_t)r * QKV_N + h * DK;
    const size_t o = ((size_t)((b << 4) + h) * SEQ + n) * DK;

    {
        const float vv = base[2 * EMBED + i];
        const __half vh = __float2half_rn(vv);
        Vh[o + i] = vh;
        Vl[o + i] = __float2half_rn(vv - __half2float(vh));
    }

    if (i < 64) {
        const float bf_base = __bfloat162float(__float2bfloat16(10000.0f));
        const float e  = (float)i * (1.0f / 64.0f);
        const float pf = (float)pow((double)bf_base, (double)e);
        const float den = __bfloat162float(__float2bfloat16(pf));
        const float invf = __fdiv_rn(1.0f, den);
        const float theta = __bfloat162float(__float2bfloat16(invf));

        const float  freq = (float)n * theta;
        const double fd = (double)freq;
        const double kq = rint(fd * 0.15915494309189535);
        const float  rr = (float)(fd - kq * 6.283185307179586);
        const float  s = sinf(rr);
        const float  c = cosf(rr);

        const float q1 = base[i];
        const float q2 = base[i + 64];
        const float k1 = base[EMBED + i];
        const float k2 = base[EMBED + i + 64];
        const float qa = q1 * c - q2 * s;
        const float qb = q1 * s + q2 * c;
        const float ka = k1 * c - k2 * s;
        const float kb = k1 * s + k2 * c;

        const __half qah = __float2half_rn(qa);
        const __half qbh = __float2half_rn(qb);
        const __half kah = __float2half_rn(ka);
        const __half kbh = __float2half_rn(kb);
        Qh[o + i]      = qah;
        Qh[o + i + 64] = qbh;
        Kh[o + i]      = kah;
        Kh[o + i + 64] = kbh;
        Ql[o + i]      = __float2half_rn(qa - __half2float(qah));
        Ql[o + i + 64] = __float2half_rn(qb - __half2float(qbh));
        Kl[o + i]      = __float2half_rn(ka - __half2float(kah));
        Kl[o + i + 64] = __float2half_rn(kb - __half2float(kbh));
    }
}

// =====================================================================
// MMA flash attention (split fp16, fp32 softmax).  Verified R7.
// Epilogue now writes hi-only output (2-term out-GEMM consumes Ah).
// =====================================================================
#define FQ_H   0
#define FQ_L   17408
#define FSTAGE 34816
#define FSTRIDE 34816
#define FKH 0
#define FKL 8704
#define FVH 17408
#define FVL 26112
#define FA_SMEM_BYTES ((FSTAGE + 2 * FSTRIDE) * 2)   // 208896

__device__ __forceinline__ void fa_load_kv(
    unsigned smem0, int s, int kb, int tid, size_t hb,
    const __half* Kh, const __half* Kl, const __half* Vh, const __half* Vl) {
    const unsigned base = smem0 + (unsigned)(FSTAGE + s * FSTRIDE) * 2u;
    #pragma unroll
    for (int i = 0; i < 16; i++) {
        const int idx = tid + i * 256;       // 0..4095
        const int a   = idx >> 10;           // 0..3
        const int row = (idx >> 4) & 63;
        const int ch  = idx & 15;
        const __half* src = (a == 0) ? Kh : (a == 1) ? Kl : (a == 2) ? Vh : Vl;
        src += hb + (size_t)(kb + row) * DK + ch * 8;
        const unsigned dst = base + (unsigned)(a * 8704 + row * 136 + ch * 8) * 2u;
        cp16(dst, src);
    }
}

__global__ __launch_bounds__(256)
void flash_attn_mma(const __half* __restrict__ Qh_g, const __half* __restrict__ Ql_g,
                    const __half* __restrict__ Kh_g, const __half* __restrict__ Kl_g,
                    const __half* __restrict__ Vh_g, const __half* __restrict__ Vl_g,
                    __half* __restrict__ Oh) {
    const int qt = gridDim.x - 1 - blockIdx.x;   // heavy tiles first
    const int bh = blockIdx.y;
    const int bIdx = bh >> 4;
    const int h = bh & 15;
    const int tid = threadIdx.x;
    const int lane = tid & 31;
    const int warp = tid >> 5;

    extern __shared__ __half fsm[];
    const unsigned smem0 = (unsigned)__cvta_generic_to_shared(fsm);

    const size_t hb = (size_t)bh * SEQ * DK;
    const int qb = qt * 128;
    const int mb = warp * 16;
    const int ktmax = 2 * qt + 1;

    // ---- load Q (hi, lo) into smem
    #pragma unroll
    for (int i = 0; i < 16; i++) {
        const int idx = tid + i * 256;       // 0..4095
        const int a   = idx >> 11;           // 0..1
        const int row = (idx >> 4) & 127;
        const int ch  = idx & 15;
        const __half* src = (a == 0) ? Qh_g : Ql_g;
        src += hb + (size_t)(qb + row) * DK + ch * 8;
        const unsigned dst = smem0 +
            (unsigned)((a == 0 ? FQ_H : FQ_L) + row * 136 + ch * 8) * 2u;
        cp16(dst, src);
    }
    cp_commit();
    fa_load_kv(smem0, 0, 0, tid, hb, Kh_g, Kl_g, Vh_g, Vl_g);
    cp_commit();
    cp_wait0();
    __syncthreads();

    float o[16][4];
    #pragma unroll
    for (int i = 0; i < 16; i++) {
        o[i][0] = 0.0f; o[i][1] = 0.0f; o[i][2] = 0.0f; o[i][3] = 0.0f;
    }
    float m0 = -1e30f, m1 = -1e30f, l0 = 0.0f, l1 = 0.0f;
    const float sc = 0.08838834764831845f;   // 1/sqrt(128)

    const unsigned sQH = smem0 + FQ_H * 2;
    const unsigned sQL = smem0 + FQ_L * 2;

    for (int kt = 0; kt <= ktmax; kt++) {
        if (kt < ktmax) {
            fa_load_kv(smem0, (kt + 1) & 1, (kt + 1) * 64, tid, hb,
                       Kh_g, Kl_g, Vh_g, Vl_g);
            cp_commit();
        }
        const unsigned stg = smem0 + (unsigned)(FSTAGE + (kt & 1) * FSTRIDE) * 2u;
        const unsigned sKH = stg + FKH * 2;
        const unsigned sKL = stg + FKL * 2;
        const unsigned sVH = stg + FVH * 2;
        const unsigned sVL = stg + FVL * 2;

        // ---- S = Q K^T (split x3)
        float s[8][4];
        #pragma unroll
        for (int j = 0; j < 8; j++) {
            s[j][0] = 0.0f; s[j][1] = 0.0f; s[j][2] = 0.0f; s[j][3] = 0.0f;
        }
        #pragma unroll 2
        for (int ks = 0; ks < 8; ks++) {
            const int kk = ks * 16;
            unsigned qfh[4], qfl[4];
            const unsigned qoff =
                (unsigned)((mb + (lane & 15)) * 136 + kk + (lane >> 4) * 8) * 2u;
            ldm_x4(qfh, sQH + qoff);
            ldm_x4(qfl, sQL + qoff);
            const int krow = ((lane >> 4) & 1) * 8 + (lane & 7);
            const int kcol = kk + ((lane >> 3) & 1) * 8;
            #pragma unroll
            for (int nb4 = 0; nb4 < 4; nb4++) {
                const unsigned koff =
                    (unsigned)((nb4 * 16 + krow) * 136 + kcol) * 2u;
                unsigned kfh[4], kfl[4];
                ldm_x4(kfh, sKH + koff);
                ldm_x4(kfl, sKL + koff);
                mma16816(s[2 * nb4],     qfh, kfh);
                mma16816(s[2 * nb4],     qfh, kfl);
                mma16816(s[2 * nb4],     qfl, kfh);
                mma16816(s[2 * nb4 + 1], qfh, kfh + 2);
                mma16816(s[2 * nb4 + 1], qfh, kfl + 2);
                mma16816(s[2 * nb4 + 1], qfl, kfh + 2);
            }
        }

        // ---- scale + causal mask
        if (kt >= 2 * qt) {
            const int row0 = qb + mb + (lane >> 2);
            const int row1 = row0 + 8;
            const int kb = kt * 64;
            #pragma unroll
            for (int j = 0; j < 8; j++) {
                const int c0 = kb + 8 * j + 2 * (lane & 3);
                s[j][0] = (c0     > row0) ? -1e30f : s[j][0] * sc;
                s[j][1] = (c0 + 1 > row0) ? -1e30f : s[j][1] * sc;
                s[j][2] = (c0     > row1) ? -1e30f : s[j][2] * sc;
                s[j][3] = (c0 + 1 > row1) ? -1e30f : s[j][3] * sc;
            }
        } else {
            #pragma unroll
            for (int j = 0; j < 8; j++) {
                s[j][0] *= sc; s[j][1] *= sc; s[j][2] *= sc; s[j][3] *= sc;
            }
        }

        // ---- row max (rows live in 4-lane groups)
        float rm0 = -1e30f, rm1 = -1e30f;
        #pragma unroll
        for (int j = 0; j < 8; j++) {
            rm0 = fmaxf(rm0, fmaxf(s[j][0], s[j][1]));
            rm1 = fmaxf(rm1, fmaxf(s[j][2], s[j][3]));
        }
        rm0 = fmaxf(rm0, __shfl_xor_sync(0xffffffffu, rm0, 1));
        rm0 = fmaxf(rm0, __shfl_xor_sync(0xffffffffu, rm0, 2));
        rm1 = fmaxf(rm1, __shfl_xor_sync(0xffffffffu, rm1, 1));
        rm1 = fmaxf(rm1, __shfl_xor_sync(0xffffffffu, rm1, 2));

        const float mn0 = fmaxf(m0, rm0);
        const float mn1 = fmaxf(m1, rm1);
        const float a0 = __expf(m0 - mn0);
        const float a1 = __expf(m1 - mn1);
        m0 = mn0; m1 = mn1;

        float sum0 = 0.0f, sum1 = 0.0f;
        #pragma unroll
        for (int j = 0; j < 8; j++) {
            const float p0 = __expf(s[j][0] - m0);
            const float p1 = __expf(s[j][1] - m0);
            const float p2 = __expf(s[j][2] - m1);
            const float p3 = __expf(s[j][3] - m1);
            s[j][0] = p0; s[j][1] = p1; s[j][2] = p2; s[j][3] = p3;
            sum0 += p0 + p1;
            sum1 += p2 + p3;
        }
        sum0 += __shfl_xor_sync(0xffffffffu, sum0, 1);
        sum0 += __shfl_xor_sync(0xffffffffu, sum0, 2);
        sum1 += __shfl_xor_sync(0xffffffffu, sum1, 1);
        sum1 += __shfl_xor_sync(0xffffffffu, sum1, 2);
        l0 = l0 * a0 + sum0;
        l1 = l1 * a1 + sum1;

        #pragma unroll
        for (int jj = 0; jj < 16; jj++) {
            o[jj][0] *= a0; o[jj][1] *= a0; o[jj][2] *= a1; o[jj][3] *= a1;
        }

        // ---- pack P into a-fragments (hi, lo)
        unsigned pah[4][4], pal[4][4];
        #pragma unroll
        for (int t = 0; t < 4; t++) {
            pack2hl(s[2 * t][0],     s[2 * t][1],     &pah[t][0], &pal[t][0]);
            pack2hl(s[2 * t][2],     s[2 * t][3],     &pah[t][1], &pal[t][1]);
            pack2hl(s[2 * t + 1][0], s[2 * t + 1][1], &pah[t][2], &pal[t][2]);
            pack2hl(s[2 * t + 1][2], s[2 * t + 1][3], &pah[t][3], &pal[t][3]);
        }

        // ---- O += P V (split x3)
        #pragma unroll 1
        for (int t = 0; t < 4; t++) {
            const int vrow = t * 16 + (lane & 15);
            const int vco = (lane >> 4) * 8;
            #pragma unroll
            for (int db4 = 0; db4 < 8; db4++) {
                const unsigned voff =
                    (unsigned)(vrow * 136 + db4 * 16 + vco) * 2u;
                unsigned vfh[4], vfl[4];
                ldm_x4_t(vfh, sVH + voff);
                ldm_x4_t(vfl, sVL + voff);
                mma16816(o[2 * db4],     pah[t], vfh);
                mma16816(o[2 * db4],     pah[t], vfl);
                mma16816(o[2 * db4],     pal[t], vfh);
                mma16816(o[2 * db4 + 1], pah[t], vfh + 2);
                mma16816(o[2 * db4 + 1], pah[t], vfl + 2);
                mma16816(o[2 * db4 + 1], pal[t], vfh + 2);
            }
        }

        if (kt < ktmax) cp_wait0();
        __syncthreads();
    }

    // ---- epilogue: normalize, write hi-only fp16, token-major
    const float inv0 = 1.0f / l0;
    const float inv1 = 1.0f / l1;
    const int row0 = qb + mb + (lane >> 2);
    const size_t tok0 = (size_t)bIdx * SEQ + row0;
    const size_t tok1 = tok0 + 8;
    const int colbase = h * DK + 2 * (lane & 3);
    #pragma unroll
    for (int jj = 0; jj < 16; jj++) {
        const int col = colbase + 8 * jj;
        *(unsigned*)(Oh + tok0 * EMBED + col) = pack2h(o[jj][0] * inv0, o[jj][1] * inv0);
        *(unsigned*)(Oh + tok1 * EMBED + col) = pack2h(o[jj][2] * inv1, o[jj][3] * inv1);
    }
}

// =====================================================================
// launch
// =====================================================================
extern "C" void kernel_launch(void* const* d_in, const int* in_sizes, int n_in,
                              void* d_out, int out_size) {
    const float* x    = 0;
    const float* Wqkv = 0;
    const float* bqkv = 0;
    const float* Wo   = 0;
    const float* bo   = 0;
    for (int i = 0; i < n_in; i++) {
        if (in_sizes[i] == 8388608)  x    = (const float*)d_in[i];
        if (in_sizes[i] == 12582912) Wqkv = (const float*)d_in[i];
        if (in_sizes[i] == 6144)     bqkv = (const float*)d_in[i];
        if (in_sizes[i] == 4194304)  Wo   = (const float*)d_in[i];
        if (in_sizes[i] == 2048)     bo   = (const float*)d_in[i];
    }
    float* out = (float*)d_out;

    float* qkv;
    __half* xh;
    __half* wqh; __half* wql;
    __half* ah;
    __half* woh; __half* wol;
    __half* qh;  __half* ql;
    __half* kh;  __half* kl;
    __half* vh;  __half* vl;
    cudaGetSymbolAddress((void**)&qkv, g_qkv);
    cudaGetSymbolAddress((void**)&xh,  g_xh);
    cudaGetSymbolAddress((void**)&wqh, g_wqh);
    cudaGetSymbolAddress((void**)&wql, g_wql);
    cudaGetSymbolAddress((void**)&ah,  g_ah);
    cudaGetSymbolAddress((void**)&woh, g_woh);
    cudaGetSymbolAddress((void**)&wol, g_wol);
    cudaGetSymbolAddress((void**)&qh,  g_qh2);
    cudaGetSymbolAddress((void**)&ql,  g_ql2);
    cudaGetSymbolAddress((void**)&kh,  g_kh2);
    cudaGetSymbolAddress((void**)&kl,  g_kl2);
    cudaGetSymbolAddress((void**)&vh,  g_vh2);
    cudaGetSymbolAddress((void**)&vl,  g_vl2);

    cudaFuncSetAttribute(hgemm2,
                         cudaFuncAttributeMaxDynamicSharedMemorySize,
                         G2_SMEM_BYTES);
    cudaFuncSetAttribute(flash_attn_mma,
                         cudaFuncAttributeMaxDynamicSharedMemorySize,
                         FA_SMEM_BYTES);

    const int NX  = TOKENS * EMBED;
    const int NWQ = EMBED * QKV_N;
    const int NWO = EMBED * EMBED;

    // 1) split inputs (x: hi only; weights: hi+lo)
    split_hi_kernel<<<NX / 1024, 256>>>(x, xh, NX);
    split_kernel<<<NWQ / 1024, 256>>>(Wqkv, wqh, wql, NWQ);
    split_kernel<<<NWO / 1024, 256>>>(Wo, woh, wol, NWO);

    // 2) qkv = x @ W_qkv + b_qkv   (2-term split fp16)
    hgemm2<<<dim3(QKV_N / 128, TOKENS / 128), 256, G2_SMEM_BYTES>>>(
        xh, wqh, wql, bqkv, qkv, TOKENS, QKV_N, EMBED);

    // 3) RoPE + split to head-major fp16 pairs
    rope_split<<<dim3(TOKENS, HEADS), 128>>>(qkv, qh, ql, kh, kl, vh, vl);

    // 4) MMA flash attention -> fp16 attn output (hi only)
    flash_attn_mma<<<dim3(SEQ / 128, BATCH * HEADS), 256, FA_SMEM_BYTES>>>(
        qh, ql, kh, kl, vh, vl, ah);

    // 5) out = attn @ W_o + b_o   (2-term split fp16)
    hgemm2<<<dim3(EMBED / 128, TOKENS / 128), 256, G2_SMEM_BYTES>>>(
        ah, woh, wol, bo, out, TOKENS, EMBED, EMBED);
}

// round 9
// speedup vs baseline: 3.9043x; 1.0364x over previous
#include <cuda_runtime.h>
#include <cuda_fp16.h>
#include <cuda_bf16.h>
#include <stdint.h>
#include <math.h>

// Problem constants
#define BATCH 2
#define SEQ   2048
#define EMBED 2048
#define HEADS 16
#define DK    128
#define TOKENS (BATCH * SEQ)          // 4096
#define QKV_N  (3 * EMBED)            // 6144

// ---------------- scratch (device globals; no allocation) ----------------
__device__ float g_qkv [(size_t)TOKENS * QKV_N];            // fp32 QKV

// fp16 operands for linear GEMMs (A-side hi only; B-side hi+lo)
__device__ __half g_xh [(size_t)TOKENS * EMBED];
__device__ __half g_wqh[(size_t)EMBED * QKV_N];
__device__ __half g_wql[(size_t)EMBED * QKV_N];
__device__ __half g_ah [(size_t)TOKENS * EMBED];   // attn out hi (from flash_attn)
__device__ __half g_woh[(size_t)EMBED * EMBED];
__device__ __half g_wol[(size_t)EMBED * EMBED];

// split fp16 Q/K/V, head-major [bh][seq][128]  (FA keeps 3-term precision)
#define HSZ ((size_t)BATCH * HEADS * SEQ * DK)
__device__ __half g_qh2[HSZ];
__device__ __half g_ql2[HSZ];
__device__ __half g_kh2[HSZ];
__device__ __half g_kl2[HSZ];
__device__ __half g_vh2[HSZ];
__device__ __half g_vl2[HSZ];

// =====================================================================
// split fp32 -> (hi, lo) fp16   (used for weights)
// =====================================================================
__global__ __launch_bounds__(256)
void split_kernel(const float* __restrict__ a, __half* __restrict__ hi,
                  __half* __restrict__ lo, int n) {
    int i = (blockIdx.x * 256 + threadIdx.x) * 4;
    if (i >= n) return;
    float4 v = *(const float4*)(a + i);
    __half h0 = __float2half_rn(v.x);
    __half h1 = __float2half_rn(v.y);
    __half h2 = __float2half_rn(v.z);
    __half h3 = __float2half_rn(v.w);
    __half l0 = __float2half_rn(v.x - __half2float(h0));
    __half l1 = __float2half_rn(v.y - __half2float(h1));
    __half l2 = __float2half_rn(v.z - __half2float(h2));
    __half l3 = __float2half_rn(v.w - __half2float(h3));
    __half2* hp = (__half2*)(hi + i);
    __half2* lp = (__half2*)(lo + i);
    hp[0] = __halves2half2(h0, h1);
    hp[1] = __halves2half2(h2, h3);
    lp[0] = __halves2half2(l0, l1);
    lp[1] = __halves2half2(l2, l3);
}

// hi-only variant (activation side of 2-term GEMM)
__global__ __launch_bounds__(256)
void split_hi_kernel(const float* __restrict__ a, __half* __restrict__ hi, int n) {
    int i = (blockIdx.x * 256 + threadIdx.x) * 4;
    if (i >= n) return;
    float4 v = *(const float4*)(a + i);
    __half2* hp = (__half2*)(hi + i);
    hp[0] = __halves2half2(__float2half_rn(v.x), __float2half_rn(v.y));
    hp[1] = __halves2half2(__float2half_rn(v.z), __float2half_rn(v.w));
}

// =====================================================================
// asm helpers
// =====================================================================
__device__ __forceinline__ void cp16(unsigned dst, const void* src) {
    asm volatile("cp.async.cg.shared.global [%0], [%1], 16;" :: "r"(dst), "l"(src));
}
__device__ __forceinline__ void cp_commit() {
    asm volatile("cp.async.commit_group;");
}
__device__ __forceinline__ void cp_wait0() {
    asm volatile("cp.async.wait_group 0;");
}
__device__ __forceinline__ void cp_wait1() {
    asm volatile("cp.async.wait_group 1;");
}
__device__ __forceinline__ void ldm_x4(unsigned* d, unsigned addr) {
    asm volatile("ldmatrix.sync.aligned.m8n8.x4.shared.b16 {%0,%1,%2,%3}, [%4];"
                 : "=r"(d[0]), "=r"(d[1]), "=r"(d[2]), "=r"(d[3]) : "r"(addr));
}
__device__ __forceinline__ void ldm_x4_t(unsigned* d, unsigned addr) {
    asm volatile("ldmatrix.sync.aligned.m8n8.x4.trans.shared.b16 {%0,%1,%2,%3}, [%4];"
                 : "=r"(d[0]), "=r"(d[1]), "=r"(d[2]), "=r"(d[3]) : "r"(addr));
}
__device__ __forceinline__ void mma16816(float* c, const unsigned* a, const unsigned* b) {
    asm volatile("mma.sync.aligned.m16n8k16.row.col.f32.f16.f16.f32 "
                 "{%0,%1,%2,%3}, {%4,%5,%6,%7}, {%8,%9}, {%0,%1,%2,%3};"
                 : "+f"(c[0]), "+f"(c[1]), "+f"(c[2]), "+f"(c[3])
                 : "r"(a[0]), "r"(a[1]), "r"(a[2]), "r"(a[3]), "r"(b[0]), "r"(b[1]));
}
// pack 2 fp32 into (hi half2, lo half2) as unsigned
__device__ __forceinline__ void pack2hl(float x, float y, unsigned* hi, unsigned* lo) {
    __half hx = __float2half_rn(x);
    __half hy = __float2half_rn(y);
    __half lx = __float2half_rn(x - __half2float(hx));
    __half ly = __float2half_rn(y - __half2float(hy));
    __half2 th = __halves2half2(hx, hy);
    __half2 tl = __halves2half2(lx, ly);
    *hi = *reinterpret_cast<unsigned*>(&th);
    *lo = *reinterpret_cast<unsigned*>(&tl);
}
__device__ __forceinline__ unsigned pack2h(float x, float y) {
    __half2 t = __halves2half2(__float2half_rn(x), __float2half_rn(y));
    return *reinterpret_cast<unsigned*>(&t);
}

// =====================================================================
// 2-term split GEMM:  C = Ah @ (Bh + Bl) + bias   (fp32 accum)
// BM=128, BN=128, BK=32, 256 threads, warp tile 64x32, m16n8k16.
// 3-stage cp.async circular pipeline, ONE barrier per k-iteration.
// =====================================================================
#define G2_AS 5120                       // 128*40 halves (Ah)
#define G2_BS 4352                       // 32*136 halves (per B array)
#define G2_STAGE (G2_AS + 2*G2_BS)       // 13824 halves per stage
#define G2_NSTAGE 3
#define G2_SMEM_BYTES (G2_NSTAGE * G2_STAGE * 2)   // 82944 B

__device__ __forceinline__ void g2_copy_stage(
    unsigned smem0, int s, int k0, int tid, int bx, int by, int N, int K,
    const __half* Ah, const __half* Bh, const __half* Bl) {
    const unsigned base = smem0 + (unsigned)(s * G2_STAGE) * 2u;
    #pragma unroll
    for (int i = 0; i < 2; i++) {
        int idx = tid + i * 256;           // 512 x 16B chunks (A)
        int row = idx >> 2;
        int ch  = idx & 3;
        const size_t go = (size_t)(by * 128 + row) * K + k0 + ch * 8;
        const unsigned so = (unsigned)(row * 40 + ch * 8) * 2u;
        cp16(base + so, Ah + go);
    }
    #pragma unroll
    for (int i = 0; i < 2; i++) {
        int idx = tid + i * 256;           // 512 x 16B chunks per B array
        int row = idx >> 4;
        int ch  = idx & 15;
        const size_t go = (size_t)(k0 + row) * N + bx * 128 + ch * 8;
        const unsigned so = (unsigned)(row * 136 + ch * 8) * 2u;
        cp16(base + G2_AS * 2 + so,             Bh + go);
        cp16(base + (G2_AS + G2_BS) * 2 + so,   Bl + go);
    }
}

__global__ __launch_bounds__(256, 2)
void hgemm2(const __half* __restrict__ Ah,
            const __half* __restrict__ Bh, const __half* __restrict__ Bl,
            const float* __restrict__ bias, float* __restrict__ C,
            int M, int N, int K) {
    extern __shared__ __half sm_h[];
    const int tid  = threadIdx.x;
    const int lane = tid & 31;
    const int warp = tid >> 5;
    const int wm = warp >> 2;
    const int wn = warp & 3;
    const int bx = blockIdx.x;
    const int by = blockIdx.y;

    const unsigned smem0 = (unsigned)__cvta_generic_to_shared(sm_h);

    float acc[4][4][4];
    #pragma unroll
    for (int i = 0; i < 4; i++) {
        #pragma unroll
        for (int j = 0; j < 4; j++) {
            acc[i][j][0] = 0.0f; acc[i][j][1] = 0.0f;
            acc[i][j][2] = 0.0f; acc[i][j][3] = 0.0f;
        }
    }

    const int nIter = K / 32;
    // prologue: stages 0, 1 in flight
    g2_copy_stage(smem0, 0, 0, tid, bx, by, N, K, Ah, Bh, Bl);
    cp_commit();
    g2_copy_stage(smem0, 1, 32, tid, bx, by, N, K, Ah, Bh, Bl);
    cp_commit();

    int stage = 0;
    for (int it = 0; it < nIter; it++) {
        // ensure stage `it` has landed (newest group may stay in flight)
        if (it + 1 < nIter) {
            cp_wait1();
        } else {
            cp_wait0();
        }
        __syncthreads();   // all warps see stage `it`; all done with stage it-1

        // refill: stage (it+2)%3 == (it-1)%3, safe after the barrier above
        if (it + 2 < nIter) {
            g2_copy_stage(smem0, (it + 2) % G2_NSTAGE, (it + 2) * 32,
                          tid, bx, by, N, K, Ah, Bh, Bl);
            cp_commit();
        }

        const unsigned base   = smem0 + (unsigned)(stage * G2_STAGE) * 2u;
        const unsigned baseA  = base;
        const unsigned baseBh = base + G2_AS * 2;
        const unsigned baseBl = base + (G2_AS + G2_BS) * 2;

        #pragma unroll
        for (int ks = 0; ks < 2; ks++) {
            const int kk = ks * 16;
            unsigned af[4][4];
            #pragma unroll
            for (int mf = 0; mf < 4; mf++) {
                const int row = wm * 64 + mf * 16 + (lane & 15);
                const int col = kk + (lane >> 4) * 8;
                const unsigned off = (unsigned)(row * 40 + col) * 2u;
                ldm_x4(af[mf], baseA + off);
            }
            unsigned bh[4][2], bl[4][2];
            #pragma unroll
            for (int nh = 0; nh < 2; nh++) {
                const int row = kk + (lane & 15);
                const int col = wn * 32 + nh * 16 + (lane >> 4) * 8;
                const unsigned off = (unsigned)(row * 136 + col) * 2u;
                unsigned d[4];
                ldm_x4_t(d, baseBh + off);
                bh[nh * 2][0]     = d[0];
                bh[nh * 2][1]     = d[1];
                bh[nh * 2 + 1][0] = d[2];
                bh[nh * 2 + 1][1] = d[3];
                ldm_x4_t(d, baseBl + off);
                bl[nh * 2][0]     = d[0];
                bl[nh * 2][1]     = d[1];
                bl[nh * 2 + 1][0] = d[2];
                bl[nh * 2 + 1][1] = d[3];
            }
            #pragma unroll
            for (int mf = 0; mf < 4; mf++) {
                #pragma unroll
                for (int nf = 0; nf < 4; nf++) {
                    mma16816(acc[mf][nf], af[mf], bh[nf]);
                    mma16816(acc[mf][nf], af[mf], bl[nf]);
                }
            }
        }

        stage = (stage + 1 == G2_NSTAGE) ? 0 : stage + 1;
    }

    #pragma unroll
    for (int mf = 0; mf < 4; mf++) {
        const int row0 = by * 128 + wm * 64 + mf * 16 + (lane >> 2);
        #pragma unroll
        for (int nf = 0; nf < 4; nf++) {
            const int col = bx * 128 + wn * 32 + nf * 8 + (lane & 3) * 2;
            const float b0 = bias[col];
            const float b1 = bias[col + 1];
            float2 v0;
            float2 v1;
            v0.x = acc[mf][nf][0] + b0; v0.y = acc[mf][nf][1] + b1;
            v1.x = acc[mf][nf][2] + b0; v1.y = acc[mf][nf][3] + b1;
            *(float2*)(C + (size_t)row0 * N + col)       = v0;
            *(float2*)(C + (size_t)(row0 + 8) * N + col) = v1;
        }
    }
}

// =====================================================================
// RoPE + split into head-major (hi, lo) fp16 Q/K/V.
// =====================================================================
__global__ __launch_bounds__(128)
void rope_split(const float* __restrict__ qkv,
                __half* __restrict__ Qh, __half* __restrict__ Ql,
                __half* __restrict__ Kh, __half* __restrict__ Kl,
                __half* __restrict__ Vh, __half* __restrict__ Vl) {
    const int r = blockIdx.x;
    const int h = blockIdx.y;
    const int b = r >> 11;
    const int n = r & 2047;
    const int i = threadIdx.x;

    const float* base = qkv + (size_t)r * QKV_N + h * DK;
    const size_t o = ((size_t)((b << 4) + h) * SEQ + n) * DK;

    {
        const float vv = base[2 * EMBED + i];
        const __half vh = __float2half_rn(vv);
        Vh[o + i] = vh;
        Vl[o + i] = __float2half_rn(vv - __half2float(vh));
    }

    if (i < 64) {
        const float bf_base = __bfloat162float(__float2bfloat16(10000.0f));
        const float e  = (float)i * (1.0f / 64.0f);
        const float pf = (float)pow((double)bf_base, (double)e);
        const float den = __bfloat162float(__float2bfloat16(pf));
        const float invf = __fdiv_rn(1.0f, den);
        const float theta = __bfloat162float(__float2bfloat16(invf));

        const float  freq = (float)n * theta;
        const double fd = (double)freq;
        const double kq = rint(fd * 0.15915494309189535);
        const float  rr = (float)(fd - kq * 6.283185307179586);
        const float  s = sinf(rr);
        const float  c = cosf(rr);

        const float q1 = base[i];
        const float q2 = base[i + 64];
        const float k1 = base[EMBED + i];
        const float k2 = base[EMBED + i + 64];
        const float qa = q1 * c - q2 * s;
        const float qb = q1 * s + q2 * c;
        const float ka = k1 * c - k2 * s;
        const float kb = k1 * s + k2 * c;

        const __half qah = __float2half_rn(qa);
        const __half qbh = __float2half_rn(qb);
        const __half kah = __float2half_rn(ka);
        const __half kbh = __float2half_rn(kb);
        Qh[o + i]      = qah;
        Qh[o + i + 64] = qbh;
        Kh[o + i]      = kah;
        Kh[o + i + 64] = kbh;
        Ql[o + i]      = __float2half_rn(qa - __half2float(qah));
        Ql[o + i + 64] = __float2half_rn(qb - __half2float(qbh));
        Kl[o + i]      = __float2half_rn(ka - __half2float(kah));
        Kl[o + i + 64] = __float2half_rn(kb - __half2float(kbh));
    }
}

// =====================================================================
// MMA flash attention (split fp16, fp32 softmax).  Verified R7/R8.
// =====================================================================
#define FQ_H   0
#define FQ_L   17408
#define FSTAGE 34816
#define FSTRIDE 34816
#define FKH 0
#define FKL 8704
#define FVH 17408
#define FVL 26112
#define FA_SMEM_BYTES ((FSTAGE + 2 * FSTRIDE) * 2)   // 208896

__device__ __forceinline__ void fa_load_kv(
    unsigned smem0, int s, int kb, int tid, size_t hb,
    const __half* Kh, const __half* Kl, const __half* Vh, const __half* Vl) {
    const unsigned base = smem0 + (unsigned)(FSTAGE + s * FSTRIDE) * 2u;
    #pragma unroll
    for (int i = 0; i < 16; i++) {
        const int idx = tid + i * 256;       // 0..4095
        const int a   = idx >> 10;           // 0..3
        const int row = (idx >> 4) & 63;
        const int ch  = idx & 15;
        const __half* src = (a == 0) ? Kh : (a == 1) ? Kl : (a == 2) ? Vh : Vl;
        src += hb + (size_t)(kb + row) * DK + ch * 8;
        const unsigned dst = base + (unsigned)(a * 8704 + row * 136 + ch * 8) * 2u;
        cp16(dst, src);
    }
}

__global__ __launch_bounds__(256)
void flash_attn_mma(const __half* __restrict__ Qh_g, const __half* __restrict__ Ql_g,
                    const __half* __restrict__ Kh_g, const __half* __restrict__ Kl_g,
                    const __half* __restrict__ Vh_g, const __half* __restrict__ Vl_g,
                    __half* __restrict__ Oh) {
    const int qt = gridDim.x - 1 - blockIdx.x;   // heavy tiles first
    const int bh = blockIdx.y;
    const int bIdx = bh >> 4;
    const int h = bh & 15;
    const int tid = threadIdx.x;
    const int lane = tid & 31;
    const int warp = tid >> 5;

    extern __shared__ __half fsm[];
    const unsigned smem0 = (unsigned)__cvta_generic_to_shared(fsm);

    const size_t hb = (size_t)bh * SEQ * DK;
    const int qb = qt * 128;
    const int mb = warp * 16;
    const int ktmax = 2 * qt + 1;

    // ---- load Q (hi, lo) into smem
    #pragma unroll
    for (int i = 0; i < 16; i++) {
        const int idx = tid + i * 256;       // 0..4095
        const int a   = idx >> 11;           // 0..1
        const int row = (idx >> 4) & 127;
        const int ch  = idx & 15;
        const __half* src = (a == 0) ? Qh_g : Ql_g;
        src += hb + (size_t)(qb + row) * DK + ch * 8;
        const unsigned dst = smem0 +
            (unsigned)((a == 0 ? FQ_H : FQ_L) + row * 136 + ch * 8) * 2u;
        cp16(dst, src);
    }
    cp_commit();
    fa_load_kv(smem0, 0, 0, tid, hb, Kh_g, Kl_g, Vh_g, Vl_g);
    cp_commit();
    cp_wait0();
    __syncthreads();

    float o[16][4];
    #pragma unroll
    for (int i = 0; i < 16; i++) {
        o[i][0] = 0.0f; o[i][1] = 0.0f; o[i][2] = 0.0f; o[i][3] = 0.0f;
    }
    float m0 = -1e30f, m1 = -1e30f, l0 = 0.0f, l1 = 0.0f;
    const float sc = 0.08838834764831845f;   // 1/sqrt(128)

    const unsigned sQH = smem0 + FQ_H * 2;
    const unsigned sQL = smem0 + FQ_L * 2;

    for (int kt = 0; kt <= ktmax; kt++) {
        if (kt < ktmax) {
            fa_load_kv(smem0, (kt + 1) & 1, (kt + 1) * 64, tid, hb,
                       Kh_g, Kl_g, Vh_g, Vl_g);
            cp_commit();
        }
        const unsigned stg = smem0 + (unsigned)(FSTAGE + (kt & 1) * FSTRIDE) * 2u;
        const unsigned sKH = stg + FKH * 2;
        const unsigned sKL = stg + FKL * 2;
        const unsigned sVH = stg + FVH * 2;
        const unsigned sVL = stg + FVL * 2;

        // ---- S = Q K^T (split x3)
        float s[8][4];
        #pragma unroll
        for (int j = 0; j < 8; j++) {
            s[j][0] = 0.0f; s[j][1] = 0.0f; s[j][2] = 0.0f; s[j][3] = 0.0f;
        }
        #pragma unroll 2
        for (int ks = 0; ks < 8; ks++) {
            const int kk = ks * 16;
            unsigned qfh[4], qfl[4];
            const unsigned qoff =
                (unsigned)((mb + (lane & 15)) * 136 + kk + (lane >> 4) * 8) * 2u;
            ldm_x4(qfh, sQH + qoff);
            ldm_x4(qfl, sQL + qoff);
            const int krow = ((lane >> 4) & 1) * 8 + (lane & 7);
            const int kcol = kk + ((lane >> 3) & 1) * 8;
            #pragma unroll
            for (int nb4 = 0; nb4 < 4; nb4++) {
                const unsigned koff =
                    (unsigned)((nb4 * 16 + krow) * 136 + kcol) * 2u;
                unsigned kfh[4], kfl[4];
                ldm_x4(kfh, sKH + koff);
                ldm_x4(kfl, sKL + koff);
                mma16816(s[2 * nb4],     qfh, kfh);
                mma16816(s[2 * nb4],     qfh, kfl);
                mma16816(s[2 * nb4],     qfl, kfh);
                mma16816(s[2 * nb4 + 1], qfh, kfh + 2);
                mma16816(s[2 * nb4 + 1], qfh, kfl + 2);
                mma16816(s[2 * nb4 + 1], qfl, kfh + 2);
            }
        }

        // ---- scale + causal mask
        if (kt >= 2 * qt) {
            const int row0 = qb + mb + (lane >> 2);
            const int row1 = row0 + 8;
            const int kb = kt * 64;
            #pragma unroll
            for (int j = 0; j < 8; j++) {
                const int c0 = kb + 8 * j + 2 * (lane & 3);
                s[j][0] = (c0     > row0) ? -1e30f : s[j][0] * sc;
                s[j][1] = (c0 + 1 > row0) ? -1e30f : s[j][1] * sc;
                s[j][2] = (c0     > row1) ? -1e30f : s[j][2] * sc;
                s[j][3] = (c0 + 1 > row1) ? -1e30f : s[j][3] * sc;
            }
        } else {
            #pragma unroll
            for (int j = 0; j < 8; j++) {
                s[j][0] *= sc; s[j][1] *= sc; s[j][2] *= sc; s[j][3] *= sc;
            }
        }

        // ---- row max (rows live in 4-lane groups)
        float rm0 = -1e30f, rm1 = -1e30f;
        #pragma unroll
        for (int j = 0; j < 8; j++) {
            rm0 = fmaxf(rm0, fmaxf(s[j][0], s[j][1]));
            rm1 = fmaxf(rm1, fmaxf(s[j][2], s[j][3]));
        }
        rm0 = fmaxf(rm0, __shfl_xor_sync(0xffffffffu, rm0, 1));
        rm0 = fmaxf(rm0, __shfl_xor_sync(0xffffffffu, rm0, 2));
        rm1 = fmaxf(rm1, __shfl_xor_sync(0xffffffffu, rm1, 1));
        rm1 = fmaxf(rm1, __shfl_xor_sync(0xffffffffu, rm1, 2));

        const float mn0 = fmaxf(m0, rm0);
        const float mn1 = fmaxf(m1, rm1);
        const float a0 = __expf(m0 - mn0);
        const float a1 = __expf(m1 - mn1);
        m0 = mn0; m1 = mn1;

        float sum0 = 0.0f, sum1 = 0.0f;
        #pragma unroll
        for (int j = 0; j < 8; j++) {
            const float p0 = __expf(s[j][0] - m0);
            const float p1 = __expf(s[j][1] - m0);
            const float p2 = __expf(s[j][2] - m1);
            const float p3 = __expf(s[j][3] - m1);
            s[j][0] = p0; s[j][1] = p1; s[j][2] = p2; s[j][3] = p3;
            sum0 += p0 + p1;
            sum1 += p2 + p3;
        }
        sum0 += __shfl_xor_sync(0xffffffffu, sum0, 1);
        sum0 += __shfl_xor_sync(0xffffffffu, sum0, 2);
        sum1 += __shfl_xor_sync(0xffffffffu, sum1, 1);
        sum1 += __shfl_xor_sync(0xffffffffu, sum1, 2);
        l0 = l0 * a0 + sum0;
        l1 = l1 * a1 + sum1;

        #pragma unroll
        for (int jj = 0; jj < 16; jj++) {
            o[jj][0] *= a0; o[jj][1] *= a0; o[jj][2] *= a1; o[jj][3] *= a1;
        }

        // ---- pack P into a-fragments (hi, lo)
        unsigned pah[4][4], pal[4][4];
        #pragma unroll
        for (int t = 0; t < 4; t++) {
            pack2hl(s[2 * t][0],     s[2 * t][1],     &pah[t][0], &pal[t][0]);
            pack2hl(s[2 * t][2],     s[2 * t][3],     &pah[t][1], &pal[t][1]);
            pack2hl(s[2 * t + 1][0], s[2 * t + 1][1], &pah[t][2], &pal[t][2]);
            pack2hl(s[2 * t + 1][2], s[2 * t + 1][3], &pah[t][3], &pal[t][3]);
        }

        // ---- O += P V (split x3)
        #pragma unroll 1
        for (int t = 0; t < 4; t++) {
            const int vrow = t * 16 + (lane & 15);
            const int vco = (lane >> 4) * 8;
            #pragma unroll
            for (int db4 = 0; db4 < 8; db4++) {
                const unsigned voff =
                    (unsigned)(vrow * 136 + db4 * 16 + vco) * 2u;
                unsigned vfh[4], vfl[4];
                ldm_x4_t(vfh, sVH + voff);
                ldm_x4_t(vfl, sVL + voff);
                mma16816(o[2 * db4],     pah[t], vfh);
                mma16816(o[2 * db4],     pah[t], vfl);
                mma16816(o[2 * db4],     pal[t], vfh);
                mma16816(o[2 * db4 + 1], pah[t], vfh + 2);
                mma16816(o[2 * db4 + 1], pah[t], vfl + 2);
                mma16816(o[2 * db4 + 1], pal[t], vfh + 2);
            }
        }

        if (kt < ktmax) cp_wait0();
        __syncthreads();
    }

    // ---- epilogue: normalize, write hi-only fp16, token-major
    const float inv0 = 1.0f / l0;
    const float inv1 = 1.0f / l1;
    const int row0 = qb + mb + (lane >> 2);
    const size_t tok0 = (size_t)bIdx * SEQ + row0;
    const size_t tok1 = tok0 + 8;
    const int colbase = h * DK + 2 * (lane & 3);
    #pragma unroll
    for (int jj = 0; jj < 16; jj++) {
        const int col = colbase + 8 * jj;
        *(unsigned*)(Oh + tok0 * EMBED + col) = pack2h(o[jj][0] * inv0, o[jj][1] * inv0);
        *(unsigned*)(Oh + tok1 * EMBED + col) = pack2h(o[jj][2] * inv1, o[jj][3] * inv1);
    }
}

// =====================================================================
// launch
// =====================================================================
extern "C" void kernel_launch(void* const* d_in, const int* in_sizes, int n_in,
                              void* d_out, int out_size) {
    const float* x    = 0;
    const float* Wqkv = 0;
    const float* bqkv = 0;
    const float* Wo   = 0;
    const float* bo   = 0;
    for (int i = 0; i < n_in; i++) {
        if (in_sizes[i] == 8388608)  x    = (const float*)d_in[i];
        if (in_sizes[i] == 12582912) Wqkv = (const float*)d_in[i];
        if (in_sizes[i] == 6144)     bqkv = (const float*)d_in[i];
        if (in_sizes[i] == 4194304)  Wo   = (const float*)d_in[i];
        if (in_sizes[i] == 2048)     bo   = (const float*)d_in[i];
    }
    float* out = (float*)d_out;

    float* qkv;
    __half* xh;
    __half* wqh; __half* wql;
    __half* ah;
    __half* woh; __half* wol;
    __half* qh;  __half* ql;
    __half* kh;  __half* kl;
    __half* vh;  __half* vl;
    cudaGetSymbolAddress((void**)&qkv, g_qkv);
    cudaGetSymbolAddress((void**)&xh,  g_xh);
    cudaGetSymbolAddress((void**)&wqh, g_wqh);
    cudaGetSymbolAddress((void**)&wql, g_wql);
    cudaGetSymbolAddress((void**)&ah,  g_ah);
    cudaGetSymbolAddress((void**)&woh, g_woh);
    cudaGetSymbolAddress((void**)&wol, g_wol);
    cudaGetSymbolAddress((void**)&qh,  g_qh2);
    cudaGetSymbolAddress((void**)&ql,  g_ql2);
    cudaGetSymbolAddress((void**)&kh,  g_kh2);
    cudaGetSymbolAddress((void**)&kl,  g_kl2);
    cudaGetSymbolAddress((void**)&vh,  g_vh2);
    cudaGetSymbolAddress((void**)&vl,  g_vl2);

    cudaFuncSetAttribute(hgemm2,
                         cudaFuncAttributeMaxDynamicSharedMemorySize,
                         G2_SMEM_BYTES);
    cudaFuncSetAttribute(flash_attn_mma,
                         cudaFuncAttributeMaxDynamicSharedMemorySize,
                         FA_SMEM_BYTES);

    const int NX  = TOKENS * EMBED;
    const int NWQ = EMBED * QKV_N;
    const int NWO = EMBED * EMBED;

    // 1) split inputs (x: hi only; weights: hi+lo)
    split_hi_kernel<<<NX / 1024, 256>>>(x, xh, NX);
    split_kernel<<<NWQ / 1024, 256>>>(Wqkv, wqh, wql, NWQ);
    split_kernel<<<NWO / 1024, 256>>>(Wo, woh, wol, NWO);

    // 2) qkv = x @ W_qkv + b_qkv   (2-term split fp16)
    hgemm2<<<dim3(QKV_N / 128, TOKENS / 128), 256, G2_SMEM_BYTES>>>(
        xh, wqh, wql, bqkv, qkv, TOKENS, QKV_N, EMBED);

    // 3) RoPE + split to head-major fp16 pairs
    rope_split<<<dim3(TOKENS, HEADS), 128>>>(qkv, qh, ql, kh, kl, vh, vl);

    // 4) MMA flash attention -> fp16 attn output (hi only)
    flash_attn_mma<<<dim3(SEQ / 128, BATCH * HEADS), 256, FA_SMEM_BYTES>>>(
        qh, ql, kh, kl, vh, vl, ah);

    // 5) out = attn @ W_o + b_o   (2-term split fp16)
    hgemm2<<<dim3(EMBED / 128, TOKENS / 128), 256, G2_SMEM_BYTES>>>(
        ah, woh, wol, bo, out, TOKENS, EMBED, EMBED);
}

// round 10
// speedup vs baseline: 4.2479x; 1.0880x over previous
#include <cuda_runtime.h>
#include <cuda_fp16.h>
#include <cuda_bf16.h>
#include <stdint.h>
#include <math.h>

// Problem constants
#define BATCH 2
#define SEQ   2048
#define EMBED 2048
#define HEADS 16
#define DK    128
#define TOKENS (BATCH * SEQ)          // 4096
#define QKV_N  (3 * EMBED)            // 6144

// ---------------- scratch (device globals; no allocation) ----------------
__device__ float g_qkv [(size_t)TOKENS * QKV_N];            // fp32 QKV

// fp16 operands for linear GEMMs (A-side hi only; B-side hi+lo)
__device__ __half g_xh [(size_t)TOKENS * EMBED];
__device__ __half g_wqh[(size_t)EMBED * QKV_N];
__device__ __half g_wql[(size_t)EMBED * QKV_N];
__device__ __half g_ah [(size_t)TOKENS * EMBED];   // attn out hi (from flash_attn)
__device__ __half g_woh[(size_t)EMBED * EMBED];
__device__ __half g_wol[(size_t)EMBED * EMBED];

// fp16 Q/K/V, head-major [bh][seq][128]; Q hi-only, K/V hi+lo
#define HSZ ((size_t)BATCH * HEADS * SEQ * DK)
__device__ __half g_qh2[HSZ];
__device__ __half g_kh2[HSZ];
__device__ __half g_kl2[HSZ];
__device__ __half g_vh2[HSZ];
__device__ __half g_vl2[HSZ];

// =====================================================================
// split fp32 -> (hi, lo) fp16   (used for weights)
// =====================================================================
__global__ __launch_bounds__(256)
void split_kernel(const float* __restrict__ a, __half* __restrict__ hi,
                  __half* __restrict__ lo, int n) {
    int i = (blockIdx.x * 256 + threadIdx.x) * 4;
    if (i >= n) return;
    float4 v = *(const float4*)(a + i);
    __half h0 = __float2half_rn(v.x);
    __half h1 = __float2half_rn(v.y);
    __half h2 = __float2half_rn(v.z);
    __half h3 = __float2half_rn(v.w);
    __half l0 = __float2half_rn(v.x - __half2float(h0));
    __half l1 = __float2half_rn(v.y - __half2float(h1));
    __half l2 = __float2half_rn(v.z - __half2float(h2));
    __half l3 = __float2half_rn(v.w - __half2float(h3));
    __half2* hp = (__half2*)(hi + i);
    __half2* lp = (__half2*)(lo + i);
    hp[0] = __halves2half2(h0, h1);
    hp[1] = __halves2half2(h2, h3);
    lp[0] = __halves2half2(l0, l1);
    lp[1] = __halves2half2(l2, l3);
}

// hi-only variant (activation side of 2-term GEMM)
__global__ __launch_bounds__(256)
void split_hi_kernel(const float* __restrict__ a, __half* __restrict__ hi, int n) {
    int i = (blockIdx.x * 256 + threadIdx.x) * 4;
    if (i >= n) return;
    float4 v = *(const float4*)(a + i);
    __half2* hp = (__half2*)(hi + i);
    hp[0] = __halves2half2(__float2half_rn(v.x), __float2half_rn(v.y));
    hp[1] = __halves2half2(__float2half_rn(v.z), __float2half_rn(v.w));
}

// =====================================================================
// asm helpers
// =====================================================================
__device__ __forceinline__ void cp16(unsigned dst, const void* src) {
    asm volatile("cp.async.cg.shared.global [%0], [%1], 16;" :: "r"(dst), "l"(src));
}
__device__ __forceinline__ void cp_commit() {
    asm volatile("cp.async.commit_group;");
}
__device__ __forceinline__ void cp_wait0() {
    asm volatile("cp.async.wait_group 0;");
}
__device__ __forceinline__ void cp_wait1() {
    asm volatile("cp.async.wait_group 1;");
}
__device__ __forceinline__ void ldm_x4(unsigned* d, unsigned addr) {
    asm volatile("ldmatrix.sync.aligned.m8n8.x4.shared.b16 {%0,%1,%2,%3}, [%4];"
                 : "=r"(d[0]), "=r"(d[1]), "=r"(d[2]), "=r"(d[3]) : "r"(addr));
}
__device__ __forceinline__ void ldm_x4_t(unsigned* d, unsigned addr) {
    asm volatile("ldmatrix.sync.aligned.m8n8.x4.trans.shared.b16 {%0,%1,%2,%3}, [%4];"
                 : "=r"(d[0]), "=r"(d[1]), "=r"(d[2]), "=r"(d[3]) : "r"(addr));
}
__device__ __forceinline__ void mma16816(float* c, const unsigned* a, const unsigned* b) {
    asm volatile("mma.sync.aligned.m16n8k16.row.col.f32.f16.f16.f32 "
                 "{%0,%1,%2,%3}, {%4,%5,%6,%7}, {%8,%9}, {%0,%1,%2,%3};"
                 : "+f"(c[0]), "+f"(c[1]), "+f"(c[2]), "+f"(c[3])
                 : "r"(a[0]), "r"(a[1]), "r"(a[2]), "r"(a[3]), "r"(b[0]), "r"(b[1]));
}
__device__ __forceinline__ unsigned pack2h(float x, float y) {
    __half2 t = __halves2half2(__float2half_rn(x), __float2half_rn(y));
    return *reinterpret_cast<unsigned*>(&t);
}

// =====================================================================
// 2-term split GEMM:  C = Ah @ (Bh + Bl) + bias   (fp32 accum)
// 3-stage cp.async circular pipeline, ONE barrier per k-iteration.
// Verified R9.
// =====================================================================
#define G2_AS 5120                       // 128*40 halves (Ah)
#define G2_BS 4352                       // 32*136 halves (per B array)
#define G2_STAGE (G2_AS + 2*G2_BS)       // 13824 halves per stage
#define G2_NSTAGE 3
#define G2_SMEM_BYTES (G2_NSTAGE * G2_STAGE * 2)   // 82944 B

__device__ __forceinline__ void g2_copy_stage(
    unsigned smem0, int s, int k0, int tid, int bx, int by, int N, int K,
    const __half* Ah, const __half* Bh, const __half* Bl) {
    const unsigned base = smem0 + (unsigned)(s * G2_STAGE) * 2u;
    #pragma unroll
    for (int i = 0; i < 2; i++) {
        int idx = tid + i * 256;           // 512 x 16B chunks (A)
        int row = idx >> 2;
        int ch  = idx & 3;
        const size_t go = (size_t)(by * 128 + row) * K + k0 + ch * 8;
        const unsigned so = (unsigned)(row * 40 + ch * 8) * 2u;
        cp16(base + so, Ah + go);
    }
    #pragma unroll
    for (int i = 0; i < 2; i++) {
        int idx = tid + i * 256;           // 512 x 16B chunks per B array
        int row = idx >> 4;
        int ch  = idx & 15;
        const size_t go = (size_t)(k0 + row) * N + bx * 128 + ch * 8;
        const unsigned so = (unsigned)(row * 136 + ch * 8) * 2u;
        cp16(base + G2_AS * 2 + so,             Bh + go);
        cp16(base + (G2_AS + G2_BS) * 2 + so,   Bl + go);
    }
}

__global__ __launch_bounds__(256, 2)
void hgemm2(const __half* __restrict__ Ah,
            const __half* __restrict__ Bh, const __half* __restrict__ Bl,
            const float* __restrict__ bias, float* __restrict__ C,
            int M, int N, int K) {
    extern __shared__ __half sm_h[];
    const int tid  = threadIdx.x;
    const int lane = tid & 31;
    const int warp = tid >> 5;
    const int wm = warp >> 2;
    const int wn = warp & 3;
    const int bx = blockIdx.x;
    const int by = blockIdx.y;

    const unsigned smem0 = (unsigned)__cvta_generic_to_shared(sm_h);

    float acc[4][4][4];
    #pragma unroll
    for (int i = 0; i < 4; i++) {
        #pragma unroll
        for (int j = 0; j < 4; j++) {
            acc[i][j][0] = 0.0f; acc[i][j][1] = 0.0f;
            acc[i][j][2] = 0.0f; acc[i][j][3] = 0.0f;
        }
    }

    const int nIter = K / 32;
    g2_copy_stage(smem0, 0, 0, tid, bx, by, N, K, Ah, Bh, Bl);
    cp_commit();
    g2_copy_stage(smem0, 1, 32, tid, bx, by, N, K, Ah, Bh, Bl);
    cp_commit();

    int stage = 0;
    for (int it = 0; it < nIter; it++) {
        if (it + 1 < nIter) {
            cp_wait1();
        } else {
            cp_wait0();
        }
        __syncthreads();

        if (it + 2 < nIter) {
            g2_copy_stage(smem0, (it + 2) % G2_NSTAGE, (it + 2) * 32,
                          tid, bx, by, N, K, Ah, Bh, Bl);
            cp_commit();
        }

        const unsigned base   = smem0 + (unsigned)(stage * G2_STAGE) * 2u;
        const unsigned baseA  = base;
        const unsigned baseBh = base + G2_AS * 2;
        const unsigned baseBl = base + (G2_AS + G2_BS) * 2;

        #pragma unroll
        for (int ks = 0; ks < 2; ks++) {
            const int kk = ks * 16;
            unsigned af[4][4];
            #pragma unroll
            for (int mf = 0; mf < 4; mf++) {
                const int row = wm * 64 + mf * 16 + (lane & 15);
                const int col = kk + (lane >> 4) * 8;
                const unsigned off = (unsigned)(row * 40 + col) * 2u;
                ldm_x4(af[mf], baseA + off);
            }
            unsigned bh[4][2], bl[4][2];
            #pragma unroll
            for (int nh = 0; nh < 2; nh++) {
                const int row = kk + (lane & 15);
                const int col = wn * 32 + nh * 16 + (lane >> 4) * 8;
                const unsigned off = (unsigned)(row * 136 + col) * 2u;
                unsigned d[4];
                ldm_x4_t(d, baseBh + off);
                bh[nh * 2][0]     = d[0];
                bh[nh * 2][1]     = d[1];
                bh[nh * 2 + 1][0] = d[2];
                bh[nh * 2 + 1][1] = d[3];
                ldm_x4_t(d, baseBl + off);
                bl[nh * 2][0]     = d[0];
                bl[nh * 2][1]     = d[1];
                bl[nh * 2 + 1][0] = d[2];
                bl[nh * 2 + 1][1] = d[3];
            }
            #pragma unroll
            for (int mf = 0; mf < 4; mf++) {
                #pragma unroll
                for (int nf = 0; nf < 4; nf++) {
                    mma16816(acc[mf][nf], af[mf], bh[nf]);
                    mma16816(acc[mf][nf], af[mf], bl[nf]);
                }
            }
        }

        stage = (stage + 1 == G2_NSTAGE) ? 0 : stage + 1;
    }

    #pragma unroll
    for (int mf = 0; mf < 4; mf++) {
        const int row0 = by * 128 + wm * 64 + mf * 16 + (lane >> 2);
        #pragma unroll
        for (int nf = 0; nf < 4; nf++) {
            const int col = bx * 128 + wn * 32 + nf * 8 + (lane & 3) * 2;
            const float b0 = bias[col];
            const float b1 = bias[col + 1];
            float2 v0;
            float2 v1;
            v0.x = acc[mf][nf][0] + b0; v0.y = acc[mf][nf][1] + b1;
            v1.x = acc[mf][nf][2] + b0; v1.y = acc[mf][nf][3] + b1;
            *(float2*)(C + (size_t)row0 * N + col)       = v0;
            *(float2*)(C + (size_t)(row0 + 8) * N + col) = v1;
        }
    }
}

// =====================================================================
// RoPE + emit head-major fp16: Q hi-only, K hi+lo, V hi+lo.
// =====================================================================
__global__ __launch_bounds__(128)
void rope_split(const float* __restrict__ qkv,
                __half* __restrict__ Qh,
                __half* __restrict__ Kh, __half* __restrict__ Kl,
                __half* __restrict__ Vh, __half* __restrict__ Vl) {
    const int r = blockIdx.x;
    const int h = blockIdx.y;
    const int b = r >> 11;
    const int n = r & 2047;
    const int i = threadIdx.x;

    const float* base = qkv + (size_t)r * QKV_N + h * DK;
    const size_t o = ((size_t)((b << 4) + h) * SEQ + n) * DK;

    {
        const float vv = base[2 * EMBED + i];
        const __half vh = __float2half_rn(vv);
        Vh[o + i] = vh;
        Vl[o + i] = __float2half_rn(vv - __half2float(vh));
    }

    if (i < 64) {
        const float bf_base = __bfloat162float(__float2bfloat16(10000.0f));
        const float e  = (float)i * (1.0f / 64.0f);
        const float pf = (float)pow((double)bf_base, (double)e);
        const float den = __bfloat162float(__float2bfloat16(pf));
        const float invf = __fdiv_rn(1.0f, den);
        const float theta = __bfloat162float(__float2bfloat16(invf));

        const float  freq = (float)n * theta;
        const double fd = (double)freq;
        const double kq = rint(fd * 0.15915494309189535);
        const float  rr = (float)(fd - kq * 6.283185307179586);
        const float  s = sinf(rr);
        const float  c = cosf(rr);

        const float q1 = base[i];
        const float q2 = base[i + 64];
        const float k1 = base[EMBED + i];
        const float k2 = base[EMBED + i + 64];
        const float qa = q1 * c - q2 * s;
        const float qb = q1 * s + q2 * c;
        const float ka = k1 * c - k2 * s;
        const float kb = k1 * s + k2 * c;

        Qh[o + i]      = __float2half_rn(qa);
        Qh[o + i + 64] = __float2half_rn(qb);
        const __half kah = __float2half_rn(ka);
        const __half kbh = __float2half_rn(kb);
        Kh[o + i]      = kah;
        Kh[o + i + 64] = kbh;
        Kl[o + i]      = __float2half_rn(ka - __half2float(kah));
        Kl[o + i + 64] = __float2half_rn(kb - __half2float(kbh));
    }
}

// =====================================================================
// MMA flash attention: Q hi-only, K/V hi+lo, P hi-only; fp32 softmax.
// BM=128, 64-key tiles, 8 warps x 16 rows, d=128.
// smem: Q hi resident (17408 halves) + 2-stage K/V (hi,lo).
// =====================================================================
#define FQSZ   17408                     // 128*136 halves
#define FSTRIDE 34816                    // 4 arrays * 64*136
#define FKH 0
#define FKL 8704
#define FVH 17408
#define FVL 26112
#define FA_SMEM_BYTES ((FQSZ + 2 * FSTRIDE) * 2)   // 174080

__device__ __forceinline__ void fa_load_kv(
    unsigned smem0, int s, int kb, int tid, size_t hb,
    const __half* Kh, const __half* Kl, const __half* Vh, const __half* Vl) {
    const unsigned base = smem0 + (unsigned)(FQSZ + s * FSTRIDE) * 2u;
    #pragma unroll
    for (int i = 0; i < 16; i++) {
        const int idx = tid + i * 256;       // 0..4095
        const int a   = idx >> 10;           // 0..3
        const int row = (idx >> 4) & 63;
        const int ch  = idx & 15;
        const __half* src = (a == 0) ? Kh : (a == 1) ? Kl : (a == 2) ? Vh : Vl;
        src += hb + (size_t)(kb + row) * DK + ch * 8;
        const unsigned dst = base + (unsigned)(a * 8704 + row * 136 + ch * 8) * 2u;
        cp16(dst, src);
    }
}

__global__ __launch_bounds__(256)
void flash_attn_mma(const __half* __restrict__ Qh_g,
                    const __half* __restrict__ Kh_g, const __half* __restrict__ Kl_g,
                    const __half* __restrict__ Vh_g, const __half* __restrict__ Vl_g,
                    __half* __restrict__ Oh) {
    const int qt = gridDim.x - 1 - blockIdx.x;   // heavy tiles first
    const int bh = blockIdx.y;
    const int bIdx = bh >> 4;
    const int h = bh & 15;
    const int tid = threadIdx.x;
    const int lane = tid & 31;
    const int warp = tid >> 5;

    extern __shared__ __half fsm[];
    const unsigned smem0 = (unsigned)__cvta_generic_to_shared(fsm);

    const size_t hb = (size_t)bh * SEQ * DK;
    const int qb = qt * 128;
    const int mb = warp * 16;
    const int ktmax = 2 * qt + 1;

    // ---- load Q hi into smem (2048 x 16B chunks)
    #pragma unroll
    for (int i = 0; i < 8; i++) {
        const int idx = tid + i * 256;       // 0..2047
        const int row = idx >> 4;
        const int ch  = idx & 15;
        const __half* src = Qh_g + hb + (size_t)(qb + row) * DK + ch * 8;
        const unsigned dst = smem0 + (unsigned)(row * 136 + ch * 8) * 2u;
        cp16(dst, src);
    }
    cp_commit();
    fa_load_kv(smem0, 0, 0, tid, hb, Kh_g, Kl_g, Vh_g, Vl_g);
    cp_commit();
    cp_wait0();
    __syncthreads();

    float o[16][4];
    #pragma unroll
    for (int i = 0; i < 16; i++) {
        o[i][0] = 0.0f; o[i][1] = 0.0f; o[i][2] = 0.0f; o[i][3] = 0.0f;
    }
    float m0 = -1e30f, m1 = -1e30f, l0 = 0.0f, l1 = 0.0f;
    const float sc = 0.08838834764831845f;   // 1/sqrt(128)

    const unsigned sQH = smem0;

    for (int kt = 0; kt <= ktmax; kt++) {
        if (kt < ktmax) {
            fa_load_kv(smem0, (kt + 1) & 1, (kt + 1) * 64, tid, hb,
                       Kh_g, Kl_g, Vh_g, Vl_g);
            cp_commit();
        }
        const unsigned stg = smem0 + (unsigned)(FQSZ + (kt & 1) * FSTRIDE) * 2u;
        const unsigned sKH = stg + FKH * 2;
        const unsigned sKL = stg + FKL * 2;
        const unsigned sVH = stg + FVH * 2;
        const unsigned sVL = stg + FVL * 2;

        // ---- S = Q K^T (Qh x (Kh + Kl))
        float s[8][4];
        #pragma unroll
        for (int j = 0; j < 8; j++) {
            s[j][0] = 0.0f; s[j][1] = 0.0f; s[j][2] = 0.0f; s[j][3] = 0.0f;
        }
        #pragma unroll 2
        for (int ks = 0; ks < 8; ks++) {
            const int kk = ks * 16;
            unsigned qfh[4];
            const unsigned qoff =
                (unsigned)((mb + (lane & 15)) * 136 + kk + (lane >> 4) * 8) * 2u;
            ldm_x4(qfh, sQH + qoff);
            const int krow = ((lane >> 4) & 1) * 8 + (lane & 7);
            const int kcol = kk + ((lane >> 3) & 1) * 8;
            #pragma unroll
            for (int nb4 = 0; nb4 < 4; nb4++) {
                const unsigned koff =
                    (unsigned)((nb4 * 16 + krow) * 136 + kcol) * 2u;
                unsigned kfh[4], kfl[4];
                ldm_x4(kfh, sKH + koff);
                ldm_x4(kfl, sKL + koff);
                mma16816(s[2 * nb4],     qfh, kfh);
                mma16816(s[2 * nb4],     qfh, kfl);
                mma16816(s[2 * nb4 + 1], qfh, kfh + 2);
                mma16816(s[2 * nb4 + 1], qfh, kfl + 2);
            }
        }

        // ---- scale + causal mask
        if (kt >= 2 * qt) {
            const int row0 = qb + mb + (lane >> 2);
            const int row1 = row0 + 8;
            const int kb = kt * 64;
            #pragma unroll
            for (int j = 0; j < 8; j++) {
                const int c0 = kb + 8 * j + 2 * (lane & 3);
                s[j][0] = (c0     > row0) ? -1e30f : s[j][0] * sc;
                s[j][1] = (c0 + 1 > row0) ? -1e30f : s[j][1] * sc;
                s[j][2] = (c0     > row1) ? -1e30f : s[j][2] * sc;
                s[j][3] = (c0 + 1 > row1) ? -1e30f : s[j][3] * sc;
            }
        } else {
            #pragma unroll
            for (int j = 0; j < 8; j++) {
                s[j][0] *= sc; s[j][1] *= sc; s[j][2] *= sc; s[j][3] *= sc;
            }
        }

        // ---- row max (rows live in 4-lane groups)
        float rm0 = -1e30f, rm1 = -1e30f;
        #pragma unroll
        for (int j = 0; j < 8; j++) {
            rm0 = fmaxf(rm0, fmaxf(s[j][0], s[j][1]));
            rm1 = fmaxf(rm1, fmaxf(s[j][2], s[j][3]));
        }
        rm0 = fmaxf(rm0, __shfl_xor_sync(0xffffffffu, rm0, 1));
        rm0 = fmaxf(rm0, __shfl_xor_sync(0xffffffffu, rm0, 2));
        rm1 = fmaxf(rm1, __shfl_xor_sync(0xffffffffu, rm1, 1));
        rm1 = fmaxf(rm1, __shfl_xor_sync(0xffffffffu, rm1, 2));

        const float mn0 = fmaxf(m0, rm0);
        const float mn1 = fmaxf(m1, rm1);
        const float a0 = __expf(m0 - mn0);
        const float a1 = __expf(m1 - mn1);
        m0 = mn0; m1 = mn1;

        float sum0 = 0.0f, sum1 = 0.0f;
        #pragma unroll
        for (int j = 0; j < 8; j++) {
            const float p0 = __expf(s[j][0] - m0);
            const float p1 = __expf(s[j][1] - m0);
            const float p2 = __expf(s[j][2] - m1);
            const float p3 = __expf(s[j][3] - m1);
            s[j][0] = p0; s[j][1] = p1; s[j][2] = p2; s[j][3] = p3;
            sum0 += p0 + p1;
            sum1 += p2 + p3;
        }
        sum0 += __shfl_xor_sync(0xffffffffu, sum0, 1);
        sum0 += __shfl_xor_sync(0xffffffffu, sum0, 2);
        sum1 += __shfl_xor_sync(0xffffffffu, sum1, 1);
        sum1 += __shfl_xor_sync(0xffffffffu, sum1, 2);
        l0 = l0 * a0 + sum0;
        l1 = l1 * a1 + sum1;

        #pragma unroll
        for (int jj = 0; jj < 16; jj++) {
            o[jj][0] *= a0; o[jj][1] *= a0; o[jj][2] *= a1; o[jj][3] *= a1;
        }

        // ---- pack P (hi only) into a-fragments
        unsigned pah[4][4];
        #pragma unroll
        for (int t = 0; t < 4; t++) {
            pah[t][0] = pack2h(s[2 * t][0],     s[2 * t][1]);
            pah[t][1] = pack2h(s[2 * t][2],     s[2 * t][3]);
            pah[t][2] = pack2h(s[2 * t + 1][0], s[2 * t + 1][1]);
            pah[t][3] = pack2h(s[2 * t + 1][2], s[2 * t + 1][3]);
        }

        // ---- O += P (Vh + Vl)
        #pragma unroll 1
        for (int t = 0; t < 4; t++) {
            const int vrow = t * 16 + (lane & 15);
            const int vco = (lane >> 4) * 8;
            #pragma unroll
            for (int db4 = 0; db4 < 8; db4++) {
                const unsigned voff =
                    (unsigned)(vrow * 136 + db4 * 16 + vco) * 2u;
                unsigned vfh[4], vfl[4];
                ldm_x4_t(vfh, sVH + voff);
                ldm_x4_t(vfl, sVL + voff);
                mma16816(o[2 * db4],     pah[t], vfh);
                mma16816(o[2 * db4],     pah[t], vfl);
                mma16816(o[2 * db4 + 1], pah[t], vfh + 2);
                mma16816(o[2 * db4 + 1], pah[t], vfl + 2);
            }
        }

        if (kt < ktmax) cp_wait0();
        __syncthreads();
    }

    // ---- epilogue: normalize, write hi-only fp16, token-major
    const float inv0 = 1.0f / l0;
    const float inv1 = 1.0f / l1;
    const int row0 = qb + mb + (lane >> 2);
    const size_t tok0 = (size_t)bIdx * SEQ + row0;
    const size_t tok1 = tok0 + 8;
    const int colbase = h * DK + 2 * (lane & 3);
    #pragma unroll
    for (int jj = 0; jj < 16; jj++) {
        const int col = colbase + 8 * jj;
        *(unsigned*)(Oh + tok0 * EMBED + col) = pack2h(o[jj][0] * inv0, o[jj][1] * inv0);
        *(unsigned*)(Oh + tok1 * EMBED + col) = pack2h(o[jj][2] * inv1, o[jj][3] * inv1);
    }
}

// =====================================================================
// launch
// =====================================================================
extern "C" void kernel_launch(void* const* d_in, const int* in_sizes, int n_in,
                              void* d_out, int out_size) {
    const float* x    = 0;
    const float* Wqkv = 0;
    const float* bqkv = 0;
    const float* Wo   = 0;
    const float* bo   = 0;
    for (int i = 0; i < n_in; i++) {
        if (in_sizes[i] == 8388608)  x    = (const float*)d_in[i];
        if (in_sizes[i] == 12582912) Wqkv = (const float*)d_in[i];
        if (in_sizes[i] == 6144)     bqkv = (const float*)d_in[i];
        if (in_sizes[i] == 4194304)  Wo   = (const float*)d_in[i];
        if (in_sizes[i] == 2048)     bo   = (const float*)d_in[i];
    }
    float* out = (float*)d_out;

    float* qkv;
    __half* xh;
    __half* wqh; __half* wql;
    __half* ah;
    __half* woh; __half* wol;
    __half* qh;
    __half* kh;  __half* kl;
    __half* vh;  __half* vl;
    cudaGetSymbolAddress((void**)&qkv, g_qkv);
    cudaGetSymbolAddress((void**)&xh,  g_xh);
    cudaGetSymbolAddress((void**)&wqh, g_wqh);
    cudaGetSymbolAddress((void**)&wql, g_wql);
    cudaGetSymbolAddress((void**)&ah,  g_ah);
    cudaGetSymbolAddress((void**)&woh, g_woh);
    cudaGetSymbolAddress((void**)&wol, g_wol);
    cudaGetSymbolAddress((void**)&qh,  g_qh2);
    cudaGetSymbolAddress((void**)&kh,  g_kh2);
    cudaGetSymbolAddress((void**)&kl,  g_kl2);
    cudaGetSymbolAddress((void**)&vh,  g_vh2);
    cudaGetSymbolAddress((void**)&vl,  g_vl2);

    cudaFuncSetAttribute(hgemm2,
                         cudaFuncAttributeMaxDynamicSharedMemorySize,
                         G2_SMEM_BYTES);
    cudaFuncSetAttribute(flash_attn_mma,
                         cudaFuncAttributeMaxDynamicSharedMemorySize,
                         FA_SMEM_BYTES);

    const int NX  = TOKENS * EMBED;
    const int NWQ = EMBED * QKV_N;
    const int NWO = EMBED * EMBED;

    // 1) split inputs (x: hi only; weights: hi+lo)
    split_hi_kernel<<<NX / 1024, 256>>>(x, xh, NX);
    split_kernel<<<NWQ / 1024, 256>>>(Wqkv, wqh, wql, NWQ);
    split_kernel<<<NWO / 1024, 256>>>(Wo, woh, wol, NWO);

    // 2) qkv = x @ W_qkv + b_qkv   (2-term split fp16)
    hgemm2<<<dim3(QKV_N / 128, TOKENS / 128), 256, G2_SMEM_BYTES>>>(
        xh, wqh, wql, bqkv, qkv, TOKENS, QKV_N, EMBED);

    // 3) RoPE: Q hi-only, K/V hi+lo
    rope_split<<<dim3(TOKENS, HEADS), 128>>>(qkv, qh, kh, kl, vh, vl);

    // 4) MMA flash attention (2-term QK and PV) -> fp16 attn output
    flash_attn_mma<<<dim3(SEQ / 128, BATCH * HEADS), 256, FA_SMEM_BYTES>>>(
        qh, kh, kl, vh, vl, ah);

    // 5) out = attn @ W_o + b_o   (2-term split fp16)
    hgemm2<<<dim3(EMBED / 128, TOKENS / 128), 256, G2_SMEM_BYTES>>>(
        ah, woh, wol, bo, out, TOKENS, EMBED, EMBED);
}